// round 1
// baseline (speedup 1.0000x reference)
#include <cuda_runtime.h>
#include <cuda_bf16.h>

#define NN 100000
#define NE 1200000
#define NG 128
#define HIDN 64
#define EPSV 1e-5f

// ---------------- scratch (static device globals; no runtime alloc) ----------------
__device__ int   g_deg[NN];
__device__ int   g_rowptr[NN + 1];
__device__ int   g_wp[NN];
__device__ int   g_col[NE];
__device__ int   g_gstart[NG + 1];
__device__ float g_h[NN * HIDN];      // conv output (pre-norm)
__device__ float g_xc[NN * HIDN];     // current normalized activations (x1 / x2)
__device__ float g_agg[NN * HIDN];    // neighbor mean
__device__ float g_stats[NG * 2 * HIDN]; // per graph: [sum(64) | sumsq(64)]
__device__ float g_pooled[NG * HIDN];
__device__ float g_WT1[8 * HIDN];     // [k(agg 0..3, x 4..7)][f]
__device__ float g_WT2[128 * HIDN];   // [k(agg 0..63, x 64..127)][f]
__device__ float g_WT3[128 * HIDN];

// ---------------- CSR build ----------------
__global__ void k_zero_deg() {
    int i = blockIdx.x * blockDim.x + threadIdx.x;
    if (i < NN) g_deg[i] = 0;
}

__global__ void k_gstart(const int* __restrict__ batch) {
    int i = blockIdx.x * blockDim.x + threadIdx.x;
    if (i < NN) {
        int b = batch[i];
        if (i == 0 || batch[i - 1] != b) g_gstart[b] = i;
    }
    if (i == 0) g_gstart[NG] = NN;
}

__global__ void k_hist(const int* __restrict__ ei) {
    int e = blockIdx.x * blockDim.x + threadIdx.x;
    if (e < NE) atomicAdd(&g_deg[ei[NE + e]], 1);
}

// single-block exclusive scan over g_deg -> g_rowptr, also fills g_wp
__global__ void k_scan() {
    const int T = 1024;
    const int IT = (NN + T - 1) / T; // 98
    __shared__ int s[T];
    int t = threadIdx.x;
    int base = t * IT;
    int local = 0;
    for (int i = 0; i < IT; i++) {
        int idx = base + i;
        if (idx < NN) local += g_deg[idx];
    }
    s[t] = local;
    __syncthreads();
    for (int off = 1; off < T; off <<= 1) {
        int v = 0;
        if (t >= off) v = s[t - off];
        __syncthreads();
        if (t >= off) s[t] += v;
        __syncthreads();
    }
    int run = (t == 0) ? 0 : s[t - 1];
    for (int i = 0; i < IT; i++) {
        int idx = base + i;
        if (idx < NN) {
            g_rowptr[idx] = run;
            g_wp[idx] = run;
            run += g_deg[idx];
        }
    }
    if (t == T - 1) g_rowptr[NN] = run;
}

__global__ void k_scatter(const int* __restrict__ ei) {
    int e = blockIdx.x * blockDim.x + threadIdx.x;
    if (e < NE) {
        int src = ei[e];
        int dst = ei[NE + e];
        int p = atomicAdd(&g_wp[dst], 1);
        g_col[p] = src;
    }
}

// ---------------- weight transpose (once per launch) ----------------
__global__ void k_transpose(const float* __restrict__ W1l, const float* __restrict__ W1r,
                            const float* __restrict__ W2l, const float* __restrict__ W2r,
                            const float* __restrict__ W3l, const float* __restrict__ W3r) {
    int i = blockIdx.x * blockDim.x + threadIdx.x;
    if (i < 512) {
        int k = i >> 6, f = i & 63;
        g_WT1[i] = (k < 4) ? W1l[f * 4 + k] : W1r[f * 4 + (k - 4)];
    }
    if (i < 8192) {
        int k = i >> 6, f = i & 63;
        g_WT2[i] = (k < 64) ? W2l[f * 64 + k] : W2r[f * 64 + (k - 64)];
        g_WT3[i] = (k < 64) ? W3l[f * 64 + k] : W3r[f * 64 + (k - 64)];
    }
}

// ---------------- layer 1 fused conv (F_in = 4) ----------------
__global__ void k_conv1(const float* __restrict__ x, const float* __restrict__ b1) {
    int v = blockIdx.x;
    int t = threadIdx.x; // 64 threads
    int r0 = g_rowptr[v], r1 = g_rowptr[v + 1];
    const float4* X4 = (const float4*)x;
    float4 acc = make_float4(0.f, 0.f, 0.f, 0.f);
    for (int e = r0 + t; e < r1; e += 64) {
        float4 xv = X4[g_col[e]];
        acc.x += xv.x; acc.y += xv.y; acc.z += xv.z; acc.w += xv.w;
    }
    __shared__ float4 red[64];
    red[t] = acc;
    __syncthreads();
    for (int s = 32; s >= 1; s >>= 1) {
        if (t < s) {
            float4 o = red[t + s];
            red[t].x += o.x; red[t].y += o.y; red[t].z += o.z; red[t].w += o.w;
        }
        __syncthreads();
    }
    float invd = 1.0f / (float)max(r1 - r0, 1);
    float4 a = red[0];
    a.x *= invd; a.y *= invd; a.z *= invd; a.w *= invd;
    float4 xv = X4[v];
    float out = b1[t]
        + g_WT1[0 * 64 + t] * a.x + g_WT1[1 * 64 + t] * a.y
        + g_WT1[2 * 64 + t] * a.z + g_WT1[3 * 64 + t] * a.w
        + g_WT1[4 * 64 + t] * xv.x + g_WT1[5 * 64 + t] * xv.y
        + g_WT1[6 * 64 + t] * xv.z + g_WT1[7 * 64 + t] * xv.w;
    g_h[v * 64 + t] = out;
}

// ---------------- per-graph sum & sumsq of g_h ----------------
__global__ void k_stats() {
    int g = blockIdx.x;
    int t = threadIdx.x; // 256
    int f = t & 63, sub = t >> 6;
    int s = g_gstart[g], e = g_gstart[g + 1];
    float sm = 0.f, sq = 0.f;
    for (int v = s + sub; v < e; v += 4) {
        float val = g_h[v * 64 + f];
        sm += val;
        sq += val * val;
    }
    __shared__ float shs[256], shq[256];
    shs[t] = sm; shq[t] = sq;
    __syncthreads();
    if (sub == 0) {
        sm = shs[t] + shs[t + 64] + shs[t + 128] + shs[t + 192];
        sq = shq[t] + shq[t + 64] + shq[t + 128] + shq[t + 192];
        g_stats[g * 128 + f] = sm;
        g_stats[g * 128 + 64 + f] = sq;
    }
}

// ---------------- graph norm (+optional residual) + relu -> g_xc ----------------
__global__ void k_norm(int use_res,
                       const float* __restrict__ gamma, const float* __restrict__ beta,
                       const float* __restrict__ alpha, const int* __restrict__ batch) {
    int i = blockIdx.x * blockDim.x + threadIdx.x; // over NN*16 float4 groups
    if (i >= NN * 16) return;
    int v = i >> 4;
    int f4 = (i & 15) * 4;
    int g = batch[v];
    float cnt = (float)(g_gstart[g + 1] - g_gstart[g]);
    float4 S = *(const float4*)&g_stats[g * 128 + f4];
    float4 Q = *(const float4*)&g_stats[g * 128 + 64 + f4];
    float4 hv = *(const float4*)&g_h[v * 64 + f4];
    float4 al = *(const float4*)&alpha[f4];
    float4 ga = *(const float4*)&gamma[f4];
    float4 be = *(const float4*)&beta[f4];
    float4 rv = make_float4(0.f, 0.f, 0.f, 0.f);
    if (use_res) rv = *(const float4*)&g_xc[v * 64 + f4];
    float ic = 1.0f / cnt;
    float4 o;
    {
        float m = S.x * ic, ex2 = Q.x * ic;
        float var = ex2 - (2.0f * al.x - al.x * al.x) * m * m;
        float y = ga.x * (hv.x - al.x * m) * rsqrtf(var + EPSV) + be.x + rv.x;
        o.x = fmaxf(y, 0.f);
    }
    {
        float m = S.y * ic, ex2 = Q.y * ic;
        float var = ex2 - (2.0f * al.y - al.y * al.y) * m * m;
        float y = ga.y * (hv.y - al.y * m) * rsqrtf(var + EPSV) + be.y + rv.y;
        o.y = fmaxf(y, 0.f);
    }
    {
        float m = S.z * ic, ex2 = Q.z * ic;
        float var = ex2 - (2.0f * al.z - al.z * al.z) * m * m;
        float y = ga.z * (hv.z - al.z * m) * rsqrtf(var + EPSV) + be.z + rv.z;
        o.z = fmaxf(y, 0.f);
    }
    {
        float m = S.w * ic, ex2 = Q.w * ic;
        float var = ex2 - (2.0f * al.w - al.w * al.w) * m * m;
        float y = ga.w * (hv.w - al.w * m) * rsqrtf(var + EPSV) + be.w + rv.w;
        o.w = fmaxf(y, 0.f);
    }
    *(float4*)&g_xc[v * 64 + f4] = o;
}

// ---------------- neighbor-mean gather (64-wide): g_xc -> g_agg ----------------
__global__ void k_gather() {
    int v = (blockIdx.x << 3) + (threadIdx.x >> 5);
    int l = threadIdx.x & 31;
    if (v >= NN) return;
    int r0 = g_rowptr[v], r1 = g_rowptr[v + 1];
    const float2* X2 = (const float2*)g_xc;
    float ax = 0.f, ay = 0.f;
    int e = r0;
    for (; e + 4 <= r1; e += 4) {
        int s0 = g_col[e], s1 = g_col[e + 1], s2 = g_col[e + 2], s3 = g_col[e + 3];
        float2 v0 = X2[s0 * 32 + l];
        float2 v1 = X2[s1 * 32 + l];
        float2 v2 = X2[s2 * 32 + l];
        float2 v3 = X2[s3 * 32 + l];
        ax += v0.x + v1.x + v2.x + v3.x;
        ay += v0.y + v1.y + v2.y + v3.y;
    }
    for (; e < r1; e++) {
        float2 v0 = X2[g_col[e] * 32 + l];
        ax += v0.x; ay += v0.y;
    }
    float invd = 1.0f / (float)max(r1 - r0, 1);
    float2 o; o.x = ax * invd; o.y = ay * invd;
    ((float2*)g_agg)[v * 32 + l] = o;
}

// ---------------- GEMM: g_h = [g_agg | g_xc] @ WT + bias ----------------
__global__ void __launch_bounds__(256) k_gemm(int layer3, const float* __restrict__ bias) {
    __shared__ float Ws[64 * 64];
    __shared__ float As[64 * 65];
    const float* WT = layer3 ? g_WT3 : g_WT2;
    int tid = threadIdx.x;
    int n0 = blockIdx.x * 64;
    int fg = tid & 15, ng = tid >> 4;
    int f0 = fg * 4, nA = ng * 4;
    float acc[4][4];
#pragma unroll
    for (int j = 0; j < 4; j++)
#pragma unroll
        for (int c = 0; c < 4; c++) acc[j][c] = 0.f;

    for (int half = 0; half < 2; half++) {
        const float* Ap = half ? g_xc : g_agg;
        __syncthreads();
        for (int i = tid; i < 4096; i += 256) Ws[i] = WT[half * 4096 + i];
        for (int i = tid; i < 4096; i += 256) {
            int r = i >> 6, c = i & 63;
            int v = n0 + r;
            As[r * 65 + c] = (v < NN) ? Ap[v * 64 + c] : 0.f;
        }
        __syncthreads();
#pragma unroll 8
        for (int k = 0; k < 64; k++) {
            float4 w = *(float4*)&Ws[k * 64 + f0];
            float a0 = As[(nA + 0) * 65 + k];
            float a1 = As[(nA + 1) * 65 + k];
            float a2 = As[(nA + 2) * 65 + k];
            float a3 = As[(nA + 3) * 65 + k];
            acc[0][0] += a0 * w.x; acc[0][1] += a0 * w.y; acc[0][2] += a0 * w.z; acc[0][3] += a0 * w.w;
            acc[1][0] += a1 * w.x; acc[1][1] += a1 * w.y; acc[1][2] += a1 * w.z; acc[1][3] += a1 * w.w;
            acc[2][0] += a2 * w.x; acc[2][1] += a2 * w.y; acc[2][2] += a2 * w.z; acc[2][3] += a2 * w.w;
            acc[3][0] += a3 * w.x; acc[3][1] += a3 * w.y; acc[3][2] += a3 * w.z; acc[3][3] += a3 * w.w;
        }
    }
    float4 bv = *(const float4*)&bias[f0];
#pragma unroll
    for (int j = 0; j < 4; j++) {
        int v = n0 + nA + j;
        if (v < NN) {
            float4 o;
            o.x = acc[j][0] + bv.x;
            o.y = acc[j][1] + bv.y;
            o.z = acc[j][2] + bv.z;
            o.w = acc[j][3] + bv.w;
            *(float4*)&g_h[v * 64 + f0] = o;
        }
    }
}

// ---------------- layer-3 norm + residual + relu fused into mean pooling ----------------
__global__ void k_norm3pool(const float* __restrict__ gamma, const float* __restrict__ beta,
                            const float* __restrict__ alpha) {
    int g = blockIdx.x;
    int t = threadIdx.x; // 256
    int f = t & 63, sub = t >> 6;
    int s = g_gstart[g], e = g_gstart[g + 1];
    float cnt = (float)(e - s);
    float ic = 1.0f / cnt;
    float S = g_stats[g * 128 + f], Q = g_stats[g * 128 + 64 + f];
    float al = alpha[f];
    float m = S * ic;
    float var = Q * ic - (2.0f * al - al * al) * m * m;
    float inv = rsqrtf(var + EPSV);
    float ga = gamma[f], be = beta[f], am = al * m;
    float p = 0.f;
    for (int v = s + sub; v < e; v += 4) {
        float y = ga * (g_h[v * 64 + f] - am) * inv + be + g_xc[v * 64 + f];
        p += fmaxf(y, 0.f);
    }
    __shared__ float sh[256];
    sh[t] = p;
    __syncthreads();
    if (sub == 0) {
        p = sh[t] + sh[t + 64] + sh[t + 128] + sh[t + 192];
        g_pooled[g * 64 + f] = p * ic; // mean pooling
    }
}

// ---------------- final linear head ----------------
__global__ void k_final(const float* __restrict__ Wlin, const float* __restrict__ blin,
                        float* __restrict__ out) {
    int g = threadIdx.x; // 128 threads
    float s0 = 0.f, s1 = 0.f, s2 = 0.f;
#pragma unroll 8
    for (int f = 0; f < 64; f++) {
        float pv = g_pooled[g * 64 + f];
        s0 += pv * Wlin[f];
        s1 += pv * Wlin[64 + f];
        s2 += pv * Wlin[128 + f];
    }
    out[g * 3 + 0] = s0 + blin[0];
    out[g * 3 + 1] = s1 + blin[1];
    out[g * 3 + 2] = s2 + blin[2];
}

// ---------------- launch ----------------
extern "C" void kernel_launch(void* const* d_in, const int* in_sizes, int n_in,
                              void* d_out, int out_size) {
    const float* x     = (const float*)d_in[0];
    const int*   ei    = (const int*)d_in[1];
    const int*   batch = (const int*)d_in[2];
    const float* W1l = (const float*)d_in[3];
    const float* b1  = (const float*)d_in[4];
    const float* W1r = (const float*)d_in[5];
    const float* W2l = (const float*)d_in[6];
    const float* b2  = (const float*)d_in[7];
    const float* W2r = (const float*)d_in[8];
    const float* W3l = (const float*)d_in[9];
    const float* b3  = (const float*)d_in[10];
    const float* W3r = (const float*)d_in[11];
    const float* g1  = (const float*)d_in[12];
    const float* be1 = (const float*)d_in[13];
    const float* a1  = (const float*)d_in[14];
    const float* g2  = (const float*)d_in[15];
    const float* be2 = (const float*)d_in[16];
    const float* a2  = (const float*)d_in[17];
    const float* g3  = (const float*)d_in[18];
    const float* be3 = (const float*)d_in[19];
    const float* a3  = (const float*)d_in[20];
    const float* Wlin = (const float*)d_in[21];
    const float* blin = (const float*)d_in[22];
    float* out = (float*)d_out;

    // CSR build + boundaries + weight transpose
    k_zero_deg<<<(NN + 255) / 256, 256>>>();
    k_gstart<<<(NN + 255) / 256, 256>>>(batch);
    k_transpose<<<32, 256>>>(W1l, W1r, W2l, W2r, W3l, W3r);
    k_hist<<<(NE + 255) / 256, 256>>>(ei);
    k_scan<<<1, 1024>>>();
    k_scatter<<<(NE + 255) / 256, 256>>>(ei);

    // layer 1
    k_conv1<<<NN, 64>>>(x, b1);
    k_stats<<<NG, 256>>>();
    k_norm<<<(NN * 16 + 255) / 256, 256>>>(0, g1, be1, a1, batch);

    // layer 2
    k_gather<<<NN / 8, 256>>>();
    k_gemm<<<(NN + 63) / 64, 256>>>(0, b2);
    k_stats<<<NG, 256>>>();
    k_norm<<<(NN * 16 + 255) / 256, 256>>>(1, g2, be2, a2, batch);

    // layer 3
    k_gather<<<NN / 8, 256>>>();
    k_gemm<<<(NN + 63) / 64, 256>>>(1, b3);
    k_stats<<<NG, 256>>>();
    k_norm3pool<<<NG, 256>>>(g3, be3, a3);

    // head
    k_final<<<1, 128>>>(Wlin, blin, out);
}

// round 2
// speedup vs baseline: 1.1773x; 1.1773x over previous
#include <cuda_runtime.h>
#include <cuda_bf16.h>

#define NN 100000
#define NE 1200000
#define NG 128
#define HIDN 64
#define EPSV 1e-5f

// ---------------- scratch (static device globals; no runtime alloc) ----------------
__device__ int   g_deg[NN];
__device__ int   g_rowptr[NN + 1];
__device__ int   g_wp[NN];
__device__ int   g_col[NE];
__device__ int   g_gstart[NG + 1];
__device__ float g_y[NN * 128];          // per-layer GEMM output [left 64 | right 64]
__device__ float g_h[NN * HIDN];         // conv output (pre-norm)
__device__ float g_xc[NN * HIDN];        // normalized activations (x1 / x2)
__device__ float g_stats[3 * NG * 128];  // per layer, per graph: [sum(64) | sumsq(64)]
__device__ float g_pooled[NG * HIDN];
__device__ float g_WT1[128 * 4];         // [n][k]  (n: 0..63 -> W1l, 64..127 -> W1r)
__device__ float g_WT2[64 * 128];        // [k][n]
__device__ float g_WT3[64 * 128];        // [k][n]

// ---------------- init: zero degree + stats ----------------
__global__ void k_zero() {
    int i = blockIdx.x * blockDim.x + threadIdx.x;
    if (i < NN) g_deg[i] = 0;
    if (i < 3 * NG * 128) g_stats[i] = 0.f;
}

__global__ void k_gstart(const int* __restrict__ batch) {
    int i = blockIdx.x * blockDim.x + threadIdx.x;
    if (i < NN) {
        int b = batch[i];
        if (i == 0 || batch[i - 1] != b) g_gstart[b] = i;
    }
    if (i == 0) g_gstart[NG] = NN;
}

__global__ void k_hist(const int* __restrict__ ei) {
    int e = blockIdx.x * blockDim.x + threadIdx.x;
    if (e < NE) atomicAdd(&g_deg[ei[NE + e]], 1);
}

// single-block coalesced tile scan (warp shuffles), exclusive -> g_rowptr, g_wp
__global__ void k_scan() {
    __shared__ int warpsum[32];
    __shared__ int carry_s;
    int t = threadIdx.x, lane = t & 31, w = t >> 5;
    if (t == 0) carry_s = 0;
    __syncthreads();
    for (int base = 0; base < NN; base += 1024) {
        int i = base + t;
        int d = (i < NN) ? g_deg[i] : 0;
        int v = d;
        #pragma unroll
        for (int o = 1; o < 32; o <<= 1) {
            int n = __shfl_up_sync(0xFFFFFFFFu, v, o);
            if (lane >= o) v += n;
        }
        if (lane == 31) warpsum[w] = v;
        __syncthreads();
        if (w == 0) {
            int s = warpsum[lane];
            #pragma unroll
            for (int o = 1; o < 32; o <<= 1) {
                int n = __shfl_up_sync(0xFFFFFFFFu, s, o);
                if (lane >= o) s += n;
            }
            warpsum[lane] = s;
        }
        __syncthreads();
        int incl = v + (w > 0 ? warpsum[w - 1] : 0);
        int total = warpsum[31];
        int ex = carry_s + incl - d;
        if (i < NN) { g_rowptr[i] = ex; g_wp[i] = ex; }
        __syncthreads();
        if (t == 0) carry_s += total;
        __syncthreads();
    }
    if (t == 0) g_rowptr[NN] = carry_s;
}

__global__ void k_scatter(const int* __restrict__ ei) {
    int e = blockIdx.x * blockDim.x + threadIdx.x;
    if (e < NE) {
        int src = ei[e];
        int dst = ei[NE + e];
        int p = atomicAdd(&g_wp[dst], 1);
        g_col[p] = src;
    }
}

// ---------------- weight pre-transpose ----------------
__global__ void k_transpose(const float* __restrict__ W1l, const float* __restrict__ W1r,
                            const float* __restrict__ W2l, const float* __restrict__ W2r,
                            const float* __restrict__ W3l, const float* __restrict__ W3r) {
    int i = blockIdx.x * blockDim.x + threadIdx.x;
    if (i < 512) {
        int n = i >> 2, k = i & 3;
        g_WT1[n * 4 + k] = (n < 64) ? W1l[n * 4 + k] : W1r[(n - 64) * 4 + k];
    }
    if (i < 8192) {
        int k = i >> 7, n = i & 127;
        g_WT2[i] = (n < 64) ? W2l[n * 64 + k] : W2r[(n - 64) * 64 + k];
        g_WT3[i] = (n < 64) ? W3l[n * 64 + k] : W3r[(n - 64) * 64 + k];
    }
}

// ---------------- layer-1 GEMM (K=4): g_y = x @ [W1l|W1r]^T ----------------
__global__ void __launch_bounds__(256) k_gemm1(const float* __restrict__ x) {
    __shared__ float4 Ws[128];   // [n] -> 4 input weights
    int tid = threadIdx.x;
    for (int i = tid; i < 128; i += 256) Ws[i] = ((const float4*)g_WT1)[i];
    __syncthreads();
    int idx = blockIdx.x * 256 + tid;
    if (idx >= NN * 32) return;
    int v = idx >> 5;
    int c = (idx & 31) * 4;
    float4 xv = ((const float4*)x)[v];
    float4 w0 = Ws[c], w1 = Ws[c + 1], w2 = Ws[c + 2], w3 = Ws[c + 3];
    float4 o;
    o.x = xv.x * w0.x + xv.y * w0.y + xv.z * w0.z + xv.w * w0.w;
    o.y = xv.x * w1.x + xv.y * w1.y + xv.z * w1.z + xv.w * w1.w;
    o.z = xv.x * w2.x + xv.y * w2.y + xv.z * w2.z + xv.w * w2.w;
    o.w = xv.x * w3.x + xv.y * w3.y + xv.z * w3.z + xv.w * w3.w;
    ((float4*)g_y)[idx] = o;
}

// ---------------- gather + bias + per-graph stats: h = mean_e y_l[src] + y_r[v] + b ---
__global__ void __launch_bounds__(256) k_aggstats(const int* __restrict__ batch,
                                                  const float* __restrict__ bias, int so) {
    int w = threadIdx.x >> 5, l = threadIdx.x & 31;
    int vbase = blockIdx.x * 128 + w * 16;
    float2 bp = ((const float2*)bias)[l];
    const float2* Y = (const float2*)g_y;
    float2* H = (float2*)g_h;
    float* st = &g_stats[so];
    float s0 = 0.f, s1 = 0.f, q0 = 0.f, q1 = 0.f;
    int curg = -1;
    for (int vi = 0; vi < 16; vi++) {
        int v = vbase + vi;
        if (v >= NN) break;
        int g = batch[v];
        if (g != curg) {
            if (curg >= 0) {
                atomicAdd(&st[curg * 128 + 2 * l],       s0);
                atomicAdd(&st[curg * 128 + 2 * l + 1],   s1);
                atomicAdd(&st[curg * 128 + 64 + 2 * l],     q0);
                atomicAdd(&st[curg * 128 + 64 + 2 * l + 1], q1);
                s0 = s1 = q0 = q1 = 0.f;
            }
            curg = g;
        }
        int r0 = g_rowptr[v], r1 = g_rowptr[v + 1];
        float ax = 0.f, ay = 0.f;
        int e = r0;
        for (; e + 4 <= r1; e += 4) {
            int a = g_col[e], b = g_col[e + 1], c = g_col[e + 2], d = g_col[e + 3];
            float2 p0 = Y[a * 64 + l];
            float2 p1 = Y[b * 64 + l];
            float2 p2 = Y[c * 64 + l];
            float2 p3 = Y[d * 64 + l];
            ax += p0.x + p1.x + p2.x + p3.x;
            ay += p0.y + p1.y + p2.y + p3.y;
        }
        for (; e < r1; e++) {
            float2 p = Y[g_col[e] * 64 + l];
            ax += p.x; ay += p.y;
        }
        float invd = 1.0f / (float)max(r1 - r0, 1);
        float2 yr = Y[v * 64 + 32 + l];
        float hx = ax * invd + yr.x + bp.x;
        float hy = ay * invd + yr.y + bp.y;
        H[v * 32 + l] = make_float2(hx, hy);
        s0 += hx; s1 += hy; q0 += hx * hx; q1 += hy * hy;
    }
    if (curg >= 0) {
        atomicAdd(&st[curg * 128 + 2 * l],       s0);
        atomicAdd(&st[curg * 128 + 2 * l + 1],   s1);
        atomicAdd(&st[curg * 128 + 64 + 2 * l],     q0);
        atomicAdd(&st[curg * 128 + 64 + 2 * l + 1], q1);
    }
}

// ---------------- fused GraphNorm(+res)+ReLU + GEMM: y = xnorm @ [Wl|Wr]^T -----------
// block: 64 rows x 128 cols, 128 threads, 8x8 per-thread. Writes g_xc (xnorm) and g_y.
__global__ void __launch_bounds__(128) k_ngemm(int l3, int use_res,
        const float* __restrict__ gamma, const float* __restrict__ beta,
        const float* __restrict__ alpha, const int* __restrict__ batch, int so) {
    __shared__ float Asm[64 * 65];       // A[row][k] at row*65+k
    __shared__ float Wsh[32 * 128];      // half-K weight tile [k][n]
    __shared__ float s_am[2][64], s_sc[2][64], s_be[64];
    const float* WT = l3 ? g_WT3 : g_WT2;
    int tid = threadIdx.x;
    int n0 = blockIdx.x * 64;
    int g0 = batch[n0];
    int split = g_gstart[g0 + 1] - n0;
    int g1 = (g0 + 1 < NG) ? g0 + 1 : g0;
    // per-tile norm tables (tile spans <= 2 graphs since graph size ~781 > 64)
    {
        int side = tid >> 6, f = tid & 63;
        int g = side ? g1 : g0;
        float cnt = (float)(g_gstart[g + 1] - g_gstart[g]);
        float ic = 1.0f / cnt;
        float m  = g_stats[so + g * 128 + f] * ic;
        float ex2 = g_stats[so + g * 128 + 64 + f] * ic;
        float al = alpha[f];
        float var = ex2 - (2.0f * al - al * al) * m * m;
        s_sc[side][f] = gamma[f] * rsqrtf(var + EPSV);
        s_am[side][f] = al * m;
        if (side == 0) s_be[f] = beta[f];
    }
    __syncthreads();
    // load A tile, apply norm (+res) + relu, store xnorm back to g_xc
    #pragma unroll
    for (int it = 0; it < 8; it++) {
        int idx = it * 512 + tid * 4;
        int row = idx >> 6, k0 = idx & 63;
        int v = n0 + row;
        float4 hv = make_float4(0.f, 0.f, 0.f, 0.f);
        float4 rv = make_float4(0.f, 0.f, 0.f, 0.f);
        if (v < NN) {
            hv = *(const float4*)&g_h[v * 64 + k0];
            if (use_res) rv = *(const float4*)&g_xc[v * 64 + k0];
        }
        int side = row >= split;
        float o[4];
        #pragma unroll
        for (int j = 0; j < 4; j++) {
            float h = (&hv.x)[j];
            float val = (h - s_am[side][k0 + j]) * s_sc[side][k0 + j] + s_be[k0 + j] + (&rv.x)[j];
            val = fmaxf(val, 0.f);
            o[j] = val;
            Asm[row * 65 + k0 + j] = val;
        }
        if (v < NN) *(float4*)&g_xc[v * 64 + k0] = *(float4*)o;
    }

    int cg = tid & 15, rg = tid >> 4;
    int c0 = cg * 8, r0 = rg * 8;
    float acc[8][8];
    #pragma unroll
    for (int i = 0; i < 8; i++)
        #pragma unroll
        for (int j = 0; j < 8; j++) acc[i][j] = 0.f;

    for (int half = 0; half < 2; half++) {
        __syncthreads();
        #pragma unroll
        for (int i = tid * 4; i < 4096; i += 512)
            *(float4*)&Wsh[i] = *(const float4*)&WT[half * 4096 + i];
        __syncthreads();
        int kb = half * 32;
        #pragma unroll 4
        for (int k = 0; k < 32; k++) {
            float4 w0 = *(float4*)&Wsh[k * 128 + c0];
            float4 w1 = *(float4*)&Wsh[k * 128 + c0 + 4];
            float wv[8] = {w0.x, w0.y, w0.z, w0.w, w1.x, w1.y, w1.z, w1.w};
            float a[8];
            #pragma unroll
            for (int r = 0; r < 8; r++) a[r] = Asm[(r0 + r) * 65 + kb + k];
            #pragma unroll
            for (int r = 0; r < 8; r++)
                #pragma unroll
                for (int c = 0; c < 8; c++) acc[r][c] += a[r] * wv[c];
        }
    }
    #pragma unroll
    for (int r = 0; r < 8; r++) {
        int v = n0 + r0 + r;
        if (v < NN) {
            *(float4*)&g_y[v * 128 + c0]     = make_float4(acc[r][0], acc[r][1], acc[r][2], acc[r][3]);
            *(float4*)&g_y[v * 128 + c0 + 4] = make_float4(acc[r][4], acc[r][5], acc[r][6], acc[r][7]);
        }
    }
}

// ---------------- layer-3 norm + residual + relu fused into mean pooling ----------------
__global__ void k_norm3pool(const float* __restrict__ gamma, const float* __restrict__ beta,
                            const float* __restrict__ alpha, int so) {
    int g = blockIdx.x;
    int t = threadIdx.x; // 256
    int f = t & 63, sub = t >> 6;
    int s = g_gstart[g], e = g_gstart[g + 1];
    float cnt = (float)(e - s);
    float ic = 1.0f / cnt;
    float S = g_stats[so + g * 128 + f], Q = g_stats[so + g * 128 + 64 + f];
    float al = alpha[f];
    float m = S * ic;
    float var = Q * ic - (2.0f * al - al * al) * m * m;
    float inv = rsqrtf(var + EPSV);
    float ga = gamma[f], be = beta[f], am = al * m;
    float p = 0.f;
    for (int v = s + sub; v < e; v += 4) {
        float y = ga * (g_h[v * 64 + f] - am) * inv + be + g_xc[v * 64 + f];
        p += fmaxf(y, 0.f);
    }
    __shared__ float sh[256];
    sh[t] = p;
    __syncthreads();
    if (sub == 0) {
        p = sh[t] + sh[t + 64] + sh[t + 128] + sh[t + 192];
        g_pooled[g * 64 + f] = p * ic;
    }
}

// ---------------- final linear head ----------------
__global__ void k_final(const float* __restrict__ Wlin, const float* __restrict__ blin,
                        float* __restrict__ out) {
    int g = threadIdx.x; // 128 threads
    float s0 = 0.f, s1 = 0.f, s2 = 0.f;
    #pragma unroll 8
    for (int f = 0; f < 64; f++) {
        float pv = g_pooled[g * 64 + f];
        s0 += pv * Wlin[f];
        s1 += pv * Wlin[64 + f];
        s2 += pv * Wlin[128 + f];
    }
    out[g * 3 + 0] = s0 + blin[0];
    out[g * 3 + 1] = s1 + blin[1];
    out[g * 3 + 2] = s2 + blin[2];
}

// ---------------- launch ----------------
extern "C" void kernel_launch(void* const* d_in, const int* in_sizes, int n_in,
                              void* d_out, int out_size) {
    const float* x     = (const float*)d_in[0];
    const int*   ei    = (const int*)d_in[1];
    const int*   batch = (const int*)d_in[2];
    const float* W1l = (const float*)d_in[3];
    const float* b1  = (const float*)d_in[4];
    const float* W1r = (const float*)d_in[5];
    const float* W2l = (const float*)d_in[6];
    const float* b2  = (const float*)d_in[7];
    const float* W2r = (const float*)d_in[8];
    const float* W3l = (const float*)d_in[9];
    const float* b3  = (const float*)d_in[10];
    const float* W3r = (const float*)d_in[11];
    const float* g1  = (const float*)d_in[12];
    const float* be1 = (const float*)d_in[13];
    const float* a1  = (const float*)d_in[14];
    const float* g2  = (const float*)d_in[15];
    const float* be2 = (const float*)d_in[16];
    const float* a2  = (const float*)d_in[17];
    const float* g3  = (const float*)d_in[18];
    const float* be3 = (const float*)d_in[19];
    const float* a3  = (const float*)d_in[20];
    const float* Wlin = (const float*)d_in[21];
    const float* blin = (const float*)d_in[22];
    float* out = (float*)d_out;

    // prep + CSR build
    k_zero<<<(NN + 255) / 256, 256>>>();
    k_gstart<<<(NN + 255) / 256, 256>>>(batch);
    k_transpose<<<32, 256>>>(W1l, W1r, W2l, W2r, W3l, W3r);
    k_hist<<<(NE + 255) / 256, 256>>>(ei);
    k_scan<<<1, 1024>>>();
    k_scatter<<<(NE + 255) / 256, 256>>>(ei);

    const int AGG_BLOCKS = (NN + 127) / 128;
    const int GEMM_BLOCKS = (NN + 63) / 64;

    // layer 1
    k_gemm1<<<(NN * 32 + 255) / 256, 256>>>(x);
    k_aggstats<<<AGG_BLOCKS, 256>>>(batch, b1, 0);
    // layer 2 (norm1 fused)
    k_ngemm<<<GEMM_BLOCKS, 128>>>(0, 0, g1, be1, a1, batch, 0);
    k_aggstats<<<AGG_BLOCKS, 256>>>(batch, b2, NG * 128);
    // layer 3 (norm2 + residual fused)
    k_ngemm<<<GEMM_BLOCKS, 128>>>(1, 1, g2, be2, a2, batch, NG * 128);
    k_aggstats<<<AGG_BLOCKS, 256>>>(batch, b3, 2 * NG * 128);

    // norm3 + residual + relu + mean pool
    k_norm3pool<<<NG, 256>>>(g3, be3, a3, 2 * NG * 128);
    // head
    k_final<<<1, 128>>>(Wlin, blin, out);
}

// round 3
// speedup vs baseline: 1.3988x; 1.1882x over previous
#include <cuda_runtime.h>
#include <cuda_bf16.h>

#define NN 100000
#define NE 1200000
#define NG 128
#define HIDN 64
#define EPSV 1e-5f

// ---------------- scratch ----------------
__device__ int   g_deg[NN];
__device__ int   g_rowptr[NN + 1];
__device__ int   g_wp[NN];
__device__ int   g_col[NE];
__device__ int   g_gstart[NG + 1];
__device__ float g_yl[NN * 64];          // GEMM left output (gathered)
__device__ float g_yr[NN * 64];          // GEMM right output (self)
__device__ float g_h[NN * HIDN];         // conv output (pre-norm)
__device__ float g_xc[NN * HIDN];        // normalized activations (x1 / x2)
__device__ float g_stats[3 * NG * 128];  // per layer, per graph: [sum(64) | sumsq(64)]
__device__ float g_pooled[NG * HIDN];
__device__ float g_WT1[128 * 4];         // [n][k]  (n: 0..63 -> W1l, 64..127 -> W1r)
__device__ float g_WT2[64 * 128];        // [k][n]
__device__ float g_WT3[64 * 128];        // [k][n]

// ---------------- merged prep: zero + gstart + weight transpose ----------------
__global__ void k_prep(const int* __restrict__ batch,
                       const float* __restrict__ W1l, const float* __restrict__ W1r,
                       const float* __restrict__ W2l, const float* __restrict__ W2r,
                       const float* __restrict__ W3l, const float* __restrict__ W3r) {
    int i = blockIdx.x * blockDim.x + threadIdx.x;
    if (i < NN) {
        g_deg[i] = 0;
        int b = batch[i];
        if (i == 0 || batch[i - 1] != b) g_gstart[b] = i;
    }
    if (i == 0) g_gstart[NG] = NN;
    if (i < 3 * NG * 128) g_stats[i] = 0.f;
    if (i < 512) {
        int n = i >> 2, k = i & 3;
        g_WT1[n * 4 + k] = (n < 64) ? W1l[n * 4 + k] : W1r[(n - 64) * 4 + k];
    }
    if (i < 8192) {
        int k = i >> 7, n = i & 127;
        g_WT2[i] = (n < 64) ? W2l[n * 64 + k] : W2r[(n - 64) * 64 + k];
        g_WT3[i] = (n < 64) ? W3l[n * 64 + k] : W3r[(n - 64) * 64 + k];
    }
}

__global__ void k_hist(const int* __restrict__ ei) {
    int e = blockIdx.x * blockDim.x + threadIdx.x;
    if (e < NE) atomicAdd(&g_deg[ei[NE + e]], 1);
}

// single-block coalesced tile scan
__global__ void k_scan() {
    __shared__ int warpsum[32];
    __shared__ int carry_s;
    int t = threadIdx.x, lane = t & 31, w = t >> 5;
    if (t == 0) carry_s = 0;
    __syncthreads();
    for (int base = 0; base < NN; base += 1024) {
        int i = base + t;
        int d = (i < NN) ? g_deg[i] : 0;
        int v = d;
        #pragma unroll
        for (int o = 1; o < 32; o <<= 1) {
            int n = __shfl_up_sync(0xFFFFFFFFu, v, o);
            if (lane >= o) v += n;
        }
        if (lane == 31) warpsum[w] = v;
        __syncthreads();
        if (w == 0) {
            int s = warpsum[lane];
            #pragma unroll
            for (int o = 1; o < 32; o <<= 1) {
                int n = __shfl_up_sync(0xFFFFFFFFu, s, o);
                if (lane >= o) s += n;
            }
            warpsum[lane] = s;
        }
        __syncthreads();
        int incl = v + (w > 0 ? warpsum[w - 1] : 0);
        int total = warpsum[31];
        int ex = carry_s + incl - d;
        if (i < NN) { g_rowptr[i] = ex; g_wp[i] = ex; }
        __syncthreads();
        if (t == 0) carry_s += total;
        __syncthreads();
    }
    if (t == 0) g_rowptr[NN] = carry_s;
}

__global__ void k_scatter(const int* __restrict__ ei) {
    int e = blockIdx.x * blockDim.x + threadIdx.x;
    if (e < NE) {
        int src = ei[e];
        int dst = ei[NE + e];
        int p = atomicAdd(&g_wp[dst], 1);
        g_col[p] = src;
    }
}

// ---------------- layer 1 fully fused: gather x (16B/edge) + K=4 GEMM + stats ----------
__global__ void __launch_bounds__(256) k_layer1(const float* __restrict__ x,
                                                const float* __restrict__ b1,
                                                const int* __restrict__ batch) {
    __shared__ float4 sA[256], sX[256];
    __shared__ float4 sW[128];
    int tid = threadIdx.x;
    if (tid < 128) sW[tid] = ((const float4*)g_WT1)[tid];
    int v = blockIdx.x * 256 + tid;
    float4 agg = make_float4(0.f, 0.f, 0.f, 0.f);
    float4 xv  = make_float4(0.f, 0.f, 0.f, 0.f);
    if (v < NN) {
        int r0 = g_rowptr[v], r1 = g_rowptr[v + 1];
        const float4* X4 = (const float4*)x;
        float4 a0 = agg, a1 = agg, a2 = agg, a3 = agg;
        int e = r0;
        for (; e + 4 <= r1; e += 4) {
            float4 p0 = X4[g_col[e]];
            float4 p1 = X4[g_col[e + 1]];
            float4 p2 = X4[g_col[e + 2]];
            float4 p3 = X4[g_col[e + 3]];
            a0.x += p0.x; a0.y += p0.y; a0.z += p0.z; a0.w += p0.w;
            a1.x += p1.x; a1.y += p1.y; a1.z += p1.z; a1.w += p1.w;
            a2.x += p2.x; a2.y += p2.y; a2.z += p2.z; a2.w += p2.w;
            a3.x += p3.x; a3.y += p3.y; a3.z += p3.z; a3.w += p3.w;
        }
        for (; e < r1; e++) {
            float4 p = X4[g_col[e]];
            a0.x += p.x; a0.y += p.y; a0.z += p.z; a0.w += p.w;
        }
        float invd = 1.0f / (float)max(r1 - r0, 1);
        agg.x = (a0.x + a1.x + a2.x + a3.x) * invd;
        agg.y = (a0.y + a1.y + a2.y + a3.y) * invd;
        agg.z = (a0.z + a1.z + a2.z + a3.z) * invd;
        agg.w = (a0.w + a1.w + a2.w + a3.w) * invd;
        xv = X4[v];
    }
    sA[tid] = agg;
    sX[tid] = xv;
    __syncthreads();

    int w = tid >> 5, l = tid & 31;
    int vb = blockIdx.x * 256 + w * 32;
    float2 bp = ((const float2*)b1)[l];
    float4 wA0 = sW[2 * l],      wA1 = sW[2 * l + 1];
    float4 wX0 = sW[64 + 2 * l], wX1 = sW[64 + 2 * l + 1];
    float2* H = (float2*)g_h;
    float s0 = 0.f, s1 = 0.f, q0 = 0.f, q1 = 0.f;
    int curg = -1;
    for (int vi = 0; vi < 32; vi++) {
        int vv = vb + vi;
        if (vv >= NN) break;
        int g = batch[vv];
        if (g != curg) {
            if (curg >= 0) {
                atomicAdd(&g_stats[curg * 128 + 2 * l],         s0);
                atomicAdd(&g_stats[curg * 128 + 2 * l + 1],     s1);
                atomicAdd(&g_stats[curg * 128 + 64 + 2 * l],     q0);
                atomicAdd(&g_stats[curg * 128 + 64 + 2 * l + 1], q1);
                s0 = s1 = q0 = q1 = 0.f;
            }
            curg = g;
        }
        float4 A = sA[w * 32 + vi];
        float4 X = sX[w * 32 + vi];
        float h0 = bp.x + wA0.x * A.x + wA0.y * A.y + wA0.z * A.z + wA0.w * A.w
                        + wX0.x * X.x + wX0.y * X.y + wX0.z * X.z + wX0.w * X.w;
        float h1 = bp.y + wA1.x * A.x + wA1.y * A.y + wA1.z * A.z + wA1.w * A.w
                        + wX1.x * X.x + wX1.y * X.y + wX1.z * X.z + wX1.w * X.w;
        H[vv * 32 + l] = make_float2(h0, h1);
        s0 += h0; s1 += h1; q0 += h0 * h0; q1 += h1 * h1;
    }
    if (curg >= 0) {
        atomicAdd(&g_stats[curg * 128 + 2 * l],         s0);
        atomicAdd(&g_stats[curg * 128 + 2 * l + 1],     s1);
        atomicAdd(&g_stats[curg * 128 + 64 + 2 * l],     q0);
        atomicAdd(&g_stats[curg * 128 + 64 + 2 * l + 1], q1);
    }
}

// ---------------- gather + bias + stats (layers 2/3): h = mean_e yl[src] + yr[v] + b ---
__global__ void __launch_bounds__(256) k_aggstats(const int* __restrict__ batch,
                                                  const float* __restrict__ bias, int so) {
    int w = threadIdx.x >> 5, l = threadIdx.x & 31;
    int vbase = blockIdx.x * 128 + w * 16;
    float2 bp = ((const float2*)bias)[l];
    const float2* Y  = (const float2*)g_yl;
    const float2* YR = (const float2*)g_yr;
    float2* H = (float2*)g_h;
    float* st = &g_stats[so];
    float s0 = 0.f, s1 = 0.f, q0 = 0.f, q1 = 0.f;
    int curg = -1;
    for (int vi = 0; vi < 16; vi++) {
        int v = vbase + vi;
        if (v >= NN) break;
        int g = batch[v];
        if (g != curg) {
            if (curg >= 0) {
                atomicAdd(&st[curg * 128 + 2 * l],         s0);
                atomicAdd(&st[curg * 128 + 2 * l + 1],     s1);
                atomicAdd(&st[curg * 128 + 64 + 2 * l],     q0);
                atomicAdd(&st[curg * 128 + 64 + 2 * l + 1], q1);
                s0 = s1 = q0 = q1 = 0.f;
            }
            curg = g;
        }
        int r0 = g_rowptr[v], r1 = g_rowptr[v + 1];
        float ax = 0.f, ay = 0.f;
        int e = r0;
        for (; e + 4 <= r1; e += 4) {
            int a = g_col[e], b = g_col[e + 1], c = g_col[e + 2], d = g_col[e + 3];
            float2 p0 = Y[a * 32 + l];
            float2 p1 = Y[b * 32 + l];
            float2 p2 = Y[c * 32 + l];
            float2 p3 = Y[d * 32 + l];
            ax += p0.x + p1.x + p2.x + p3.x;
            ay += p0.y + p1.y + p2.y + p3.y;
        }
        for (; e < r1; e++) {
            float2 p = Y[g_col[e] * 32 + l];
            ax += p.x; ay += p.y;
        }
        float invd = 1.0f / (float)max(r1 - r0, 1);
        float2 yr = YR[v * 32 + l];
        float hx = ax * invd + yr.x + bp.x;
        float hy = ay * invd + yr.y + bp.y;
        H[v * 32 + l] = make_float2(hx, hy);
        s0 += hx; s1 += hy; q0 += hx * hx; q1 += hy * hy;
    }
    if (curg >= 0) {
        atomicAdd(&st[curg * 128 + 2 * l],         s0);
        atomicAdd(&st[curg * 128 + 2 * l + 1],     s1);
        atomicAdd(&st[curg * 128 + 64 + 2 * l],     q0);
        atomicAdd(&st[curg * 128 + 64 + 2 * l + 1], q1);
    }
}

// ---------------- fused GraphNorm(+res)+ReLU + GEMM (f32x2 packed FMA) ----------------
__global__ void __launch_bounds__(128) k_ngemm(int l3, int use_res,
        const float* __restrict__ gamma, const float* __restrict__ beta,
        const float* __restrict__ alpha, const int* __restrict__ batch, int so) {
    __shared__ float Asm[64 * 65];
    __shared__ float Wsh[32 * 128];
    __shared__ float s_am[2][64], s_sc[2][64], s_be[64];
    const float* WT = l3 ? g_WT3 : g_WT2;
    int tid = threadIdx.x;
    int n0 = blockIdx.x * 64;
    int g0 = batch[n0];
    int split = g_gstart[g0 + 1] - n0;
    int g1 = (g0 + 1 < NG) ? g0 + 1 : g0;
    {
        int side = tid >> 6, f = tid & 63;
        int g = side ? g1 : g0;
        float cnt = (float)(g_gstart[g + 1] - g_gstart[g]);
        float ic = 1.0f / cnt;
        float m   = g_stats[so + g * 128 + f] * ic;
        float ex2 = g_stats[so + g * 128 + 64 + f] * ic;
        float al = alpha[f];
        float var = ex2 - (2.0f * al - al * al) * m * m;
        s_sc[side][f] = gamma[f] * rsqrtf(var + EPSV);
        s_am[side][f] = al * m;
        if (side == 0) s_be[f] = beta[f];
    }
    __syncthreads();
    #pragma unroll
    for (int it = 0; it < 8; it++) {
        int idx = it * 512 + tid * 4;
        int row = idx >> 6, k0 = idx & 63;
        int v = n0 + row;
        float4 hv = make_float4(0.f, 0.f, 0.f, 0.f);
        float4 rv = make_float4(0.f, 0.f, 0.f, 0.f);
        if (v < NN) {
            hv = *(const float4*)&g_h[v * 64 + k0];
            if (use_res) rv = *(const float4*)&g_xc[v * 64 + k0];
        }
        int side = row >= split;
        float o[4];
        #pragma unroll
        for (int j = 0; j < 4; j++) {
            float h = (&hv.x)[j];
            float val = (h - s_am[side][k0 + j]) * s_sc[side][k0 + j] + s_be[k0 + j] + (&rv.x)[j];
            val = fmaxf(val, 0.f);
            o[j] = val;
            Asm[row * 65 + k0 + j] = val;
        }
        if (v < NN) *(float4*)&g_xc[v * 64 + k0] = *(float4*)o;
    }

    int cg = tid & 15, rg = tid >> 4;
    int c0 = cg * 8, r0 = rg * 8;
    unsigned long long acc[8][4];
    #pragma unroll
    for (int r = 0; r < 8; r++)
        #pragma unroll
        for (int j = 0; j < 4; j++) acc[r][j] = 0ull;

    for (int half = 0; half < 2; half++) {
        __syncthreads();
        #pragma unroll
        for (int i = tid * 4; i < 4096; i += 512)
            *(float4*)&Wsh[i] = *(const float4*)&WT[half * 4096 + i];
        __syncthreads();
        int kb = half * 32;
        #pragma unroll 8
        for (int k = 0; k < 32; k++) {
            const unsigned long long* wp = (const unsigned long long*)&Wsh[k * 128 + c0];
            unsigned long long w0 = wp[0], w1 = wp[1], w2 = wp[2], w3 = wp[3];
            #pragma unroll
            for (int r = 0; r < 8; r++) {
                unsigned int ai = __float_as_uint(Asm[(r0 + r) * 65 + kb + k]);
                unsigned long long a2;
                asm("mov.b64 %0, {%1, %1};" : "=l"(a2) : "r"(ai));
                asm("fma.rn.f32x2 %0, %1, %2, %0;" : "+l"(acc[r][0]) : "l"(a2), "l"(w0));
                asm("fma.rn.f32x2 %0, %1, %2, %0;" : "+l"(acc[r][1]) : "l"(a2), "l"(w1));
                asm("fma.rn.f32x2 %0, %1, %2, %0;" : "+l"(acc[r][2]) : "l"(a2), "l"(w2));
                asm("fma.rn.f32x2 %0, %1, %2, %0;" : "+l"(acc[r][3]) : "l"(a2), "l"(w3));
            }
        }
    }
    float* outbuf = (c0 < 64) ? g_yl : g_yr;
    int oc = (c0 < 64) ? c0 : c0 - 64;
    #pragma unroll
    for (int r = 0; r < 8; r++) {
        int v = n0 + r0 + r;
        if (v < NN) {
            float o[8];
            #pragma unroll
            for (int j = 0; j < 4; j++) {
                unsigned int lo, hi;
                asm("mov.b64 {%0, %1}, %2;" : "=r"(lo), "=r"(hi) : "l"(acc[r][j]));
                o[2 * j]     = __uint_as_float(lo);
                o[2 * j + 1] = __uint_as_float(hi);
            }
            *(float4*)&outbuf[v * 64 + oc]     = *(float4*)&o[0];
            *(float4*)&outbuf[v * 64 + oc + 4] = *(float4*)&o[4];
        }
    }
}

// ---------------- layer-3 norm + residual + relu fused into mean pooling --------------
__global__ void k_norm3pool(const float* __restrict__ gamma, const float* __restrict__ beta,
                            const float* __restrict__ alpha, int so) {
    int g = blockIdx.x;
    int t = threadIdx.x; // 256
    int f = t & 63, sub = t >> 6;
    int s = g_gstart[g], e = g_gstart[g + 1];
    float cnt = (float)(e - s);
    float ic = 1.0f / cnt;
    float S = g_stats[so + g * 128 + f], Q = g_stats[so + g * 128 + 64 + f];
    float al = alpha[f];
    float m = S * ic;
    float var = Q * ic - (2.0f * al - al * al) * m * m;
    float inv = rsqrtf(var + EPSV);
    float ga = gamma[f], be = beta[f], am = al * m;
    float p = 0.f;
    for (int v = s + sub; v < e; v += 4) {
        float y = ga * (g_h[v * 64 + f] - am) * inv + be + g_xc[v * 64 + f];
        p += fmaxf(y, 0.f);
    }
    __shared__ float sh[256];
    sh[t] = p;
    __syncthreads();
    if (sub == 0) {
        p = sh[t] + sh[t + 64] + sh[t + 128] + sh[t + 192];
        g_pooled[g * 64 + f] = p * ic;
    }
}

// ---------------- final linear head ----------------
__global__ void k_final(const float* __restrict__ Wlin, const float* __restrict__ blin,
                        float* __restrict__ out) {
    int g = threadIdx.x; // 128
    float s0 = 0.f, s1 = 0.f, s2 = 0.f;
    #pragma unroll 8
    for (int f = 0; f < 64; f++) {
        float pv = g_pooled[g * 64 + f];
        s0 += pv * Wlin[f];
        s1 += pv * Wlin[64 + f];
        s2 += pv * Wlin[128 + f];
    }
    out[g * 3 + 0] = s0 + blin[0];
    out[g * 3 + 1] = s1 + blin[1];
    out[g * 3 + 2] = s2 + blin[2];
}

// ---------------- launch ----------------
extern "C" void kernel_launch(void* const* d_in, const int* in_sizes, int n_in,
                              void* d_out, int out_size) {
    const float* x     = (const float*)d_in[0];
    const int*   ei    = (const int*)d_in[1];
    const int*   batch = (const int*)d_in[2];
    const float* W1l = (const float*)d_in[3];
    const float* b1  = (const float*)d_in[4];
    const float* W1r = (const float*)d_in[5];
    const float* W2l = (const float*)d_in[6];
    const float* b2  = (const float*)d_in[7];
    const float* W2r = (const float*)d_in[8];
    const float* W3l = (const float*)d_in[9];
    const float* b3  = (const float*)d_in[10];
    const float* W3r = (const float*)d_in[11];
    const float* g1  = (const float*)d_in[12];
    const float* be1 = (const float*)d_in[13];
    const float* a1  = (const float*)d_in[14];
    const float* g2  = (const float*)d_in[15];
    const float* be2 = (const float*)d_in[16];
    const float* a2  = (const float*)d_in[17];
    const float* g3  = (const float*)d_in[18];
    const float* be3 = (const float*)d_in[19];
    const float* a3  = (const float*)d_in[20];
    const float* Wlin = (const float*)d_in[21];
    const float* blin = (const float*)d_in[22];
    float* out = (float*)d_out;

    k_prep<<<(NN + 255) / 256, 256>>>(batch, W1l, W1r, W2l, W2r, W3l, W3r);
    k_hist<<<(NE + 255) / 256, 256>>>(ei);
    k_scan<<<1, 1024>>>();
    k_scatter<<<(NE + 255) / 256, 256>>>(ei);

    const int AGG_BLOCKS = (NN + 127) / 128;
    const int GEMM_BLOCKS = (NN + 63) / 64;

    // layer 1 (fused gather-x + K=4 GEMM + stats)
    k_layer1<<<(NN + 255) / 256, 256>>>(x, b1, batch);
    // layer 2 (norm1 fused into GEMM)
    k_ngemm<<<GEMM_BLOCKS, 128>>>(0, 0, g1, be1, a1, batch, 0);
    k_aggstats<<<AGG_BLOCKS, 256>>>(batch, b2, NG * 128);
    // layer 3 (norm2 + residual fused into GEMM)
    k_ngemm<<<GEMM_BLOCKS, 128>>>(1, 1, g2, be2, a2, batch, NG * 128);
    k_aggstats<<<AGG_BLOCKS, 256>>>(batch, b3, 2 * NG * 128);

    k_norm3pool<<<NG, 256>>>(g3, be3, a3, 2 * NG * 128);
    k_final<<<1, 128>>>(Wlin, blin, out);
}

// round 4
// speedup vs baseline: 1.6451x; 1.1761x over previous
#include <cuda_runtime.h>
#include <cuda_bf16.h>
#include <cuda_fp16.h>

#define NN 100000
#define NE 1200000
#define NG 128
#define HIDN 64
#define EPSV 1e-5f
#define NSC ((NN + 1023) / 1024)   // 98 scan blocks

// ---------------- scratch ----------------
__device__ int    g_deg[NN];
__device__ int    g_rowptr[NN + 1];
__device__ int    g_wp[NN];
__device__ int    g_col[NE];
__device__ int    g_gstart[NG + 1];
__device__ int    g_bsum[NSC];
__device__ __half g_ylh[NN * 64];        // GEMM left output (gathered), fp16
__device__ float  g_yr[NN * 64];         // GEMM right output (self), fp32
__device__ float  g_h[NN * HIDN];        // conv output (pre-norm)
__device__ float  g_xc[NN * HIDN];       // normalized activations (x1 / x2)
__device__ float  g_stats[3 * NG * 128]; // per layer, per graph: [sum(64) | sumsq(64)]
__device__ float  g_pooled[NG * HIDN];
__device__ float  g_WT1[128 * 4];        // [n][k]  (n: 0..63 -> W1l, 64..127 -> W1r)
__device__ float  g_WT2[64 * 128];       // [k][n]
__device__ float  g_WT3[64 * 128];       // [k][n]

// ---------------- merged prep: zero + gstart + weight transpose ----------------
__global__ void k_prep(const int* __restrict__ batch,
                       const float* __restrict__ W1l, const float* __restrict__ W1r,
                       const float* __restrict__ W2l, const float* __restrict__ W2r,
                       const float* __restrict__ W3l, const float* __restrict__ W3r) {
    int i = blockIdx.x * blockDim.x + threadIdx.x;
    if (i < NN) {
        g_deg[i] = 0;
        int b = batch[i];
        if (i == 0 || batch[i - 1] != b) g_gstart[b] = i;
    }
    if (i == 0) g_gstart[NG] = NN;
    if (i < 3 * NG * 128) g_stats[i] = 0.f;
    if (i < 512) {
        int n = i >> 2, k = i & 3;
        g_WT1[n * 4 + k] = (n < 64) ? W1l[n * 4 + k] : W1r[(n - 64) * 4 + k];
    }
    if (i < 8192) {
        int k = i >> 7, n = i & 127;
        g_WT2[i] = (n < 64) ? W2l[n * 64 + k] : W2r[(n - 64) * 64 + k];
        g_WT3[i] = (n < 64) ? W3l[n * 64 + k] : W3r[(n - 64) * 64 + k];
    }
}

__global__ void k_hist(const int* __restrict__ ei) {
    int e = blockIdx.x * blockDim.x + threadIdx.x;
    if (e < NE) atomicAdd(&g_deg[ei[NE + e]], 1);
}

// ---------------- parallel 3-phase scan ----------------
__global__ void k_scan1() {
    __shared__ int ws[32];
    int b = blockIdx.x, t = threadIdx.x, lane = t & 31, w = t >> 5;
    int i = b * 1024 + t;
    int v = (i < NN) ? g_deg[i] : 0;
    #pragma unroll
    for (int o = 16; o >= 1; o >>= 1) v += __shfl_xor_sync(0xFFFFFFFFu, v, o);
    if (lane == 0) ws[w] = v;
    __syncthreads();
    if (t < 32) {
        int s = ws[t];
        #pragma unroll
        for (int o = 16; o >= 1; o >>= 1) s += __shfl_xor_sync(0xFFFFFFFFu, s, o);
        if (t == 0) g_bsum[b] = s;
    }
}

__global__ void k_scan2() {
    __shared__ int wsum[4];
    int t = threadIdx.x, lane = t & 31, w = t >> 5; // 128 threads
    int v0 = (t < NSC) ? g_bsum[t] : 0;
    int v = v0;
    #pragma unroll
    for (int o = 1; o < 32; o <<= 1) {
        int n = __shfl_up_sync(0xFFFFFFFFu, v, o);
        if (lane >= o) v += n;
    }
    if (lane == 31) wsum[w] = v;
    __syncthreads();
    int off = 0;
    for (int j = 0; j < w; j++) off += wsum[j];
    int incl = v + off;
    if (t < NSC) g_bsum[t] = incl - v0;
    if (t == 127) g_rowptr[NN] = incl;
}

__global__ void k_scan3() {
    __shared__ int warpsum[32];
    int b = blockIdx.x, t = threadIdx.x, lane = t & 31, w = t >> 5;
    int i = b * 1024 + t;
    int d = (i < NN) ? g_deg[i] : 0;
    int v = d;
    #pragma unroll
    for (int o = 1; o < 32; o <<= 1) {
        int n = __shfl_up_sync(0xFFFFFFFFu, v, o);
        if (lane >= o) v += n;
    }
    if (lane == 31) warpsum[w] = v;
    __syncthreads();
    if (w == 0) {
        int s = warpsum[lane];
        #pragma unroll
        for (int o = 1; o < 32; o <<= 1) {
            int n = __shfl_up_sync(0xFFFFFFFFu, s, o);
            if (lane >= o) s += n;
        }
        warpsum[lane] = s;
    }
    __syncthreads();
    int ex = g_bsum[b] + v - d + (w > 0 ? warpsum[w - 1] : 0);
    if (i < NN) { g_rowptr[i] = ex; g_wp[i] = ex; }
}

__global__ void k_scatter(const int* __restrict__ ei) {
    int e = blockIdx.x * blockDim.x + threadIdx.x;
    if (e < NE) {
        int src = ei[e];
        int dst = ei[NE + e];
        int p = atomicAdd(&g_wp[dst], 1);
        g_col[p] = src;
    }
}

// ---------------- layer 1 fully fused: gather x (16B/edge) + K=4 GEMM + stats ----------
__global__ void __launch_bounds__(256) k_layer1(const float* __restrict__ x,
                                                const float* __restrict__ b1,
                                                const int* __restrict__ batch) {
    __shared__ float4 sA[256], sX[256];
    __shared__ float4 sW[128];
    int tid = threadIdx.x;
    if (tid < 128) sW[tid] = ((const float4*)g_WT1)[tid];
    int v = blockIdx.x * 256 + tid;
    float4 agg = make_float4(0.f, 0.f, 0.f, 0.f);
    float4 xv  = make_float4(0.f, 0.f, 0.f, 0.f);
    if (v < NN) {
        int r0 = g_rowptr[v], r1 = g_rowptr[v + 1];
        const float4* X4 = (const float4*)x;
        float4 a0 = agg, a1 = agg, a2 = agg, a3 = agg;
        int e = r0;
        for (; e + 4 <= r1; e += 4) {
            float4 p0 = X4[g_col[e]];
            float4 p1 = X4[g_col[e + 1]];
            float4 p2 = X4[g_col[e + 2]];
            float4 p3 = X4[g_col[e + 3]];
            a0.x += p0.x; a0.y += p0.y; a0.z += p0.z; a0.w += p0.w;
            a1.x += p1.x; a1.y += p1.y; a1.z += p1.z; a1.w += p1.w;
            a2.x += p2.x; a2.y += p2.y; a2.z += p2.z; a2.w += p2.w;
            a3.x += p3.x; a3.y += p3.y; a3.z += p3.z; a3.w += p3.w;
        }
        for (; e < r1; e++) {
            float4 p = X4[g_col[e]];
            a0.x += p.x; a0.y += p.y; a0.z += p.z; a0.w += p.w;
        }
        float invd = 1.0f / (float)max(r1 - r0, 1);
        agg.x = (a0.x + a1.x + a2.x + a3.x) * invd;
        agg.y = (a0.y + a1.y + a2.y + a3.y) * invd;
        agg.z = (a0.z + a1.z + a2.z + a3.z) * invd;
        agg.w = (a0.w + a1.w + a2.w + a3.w) * invd;
        xv = X4[v];
    }
    sA[tid] = agg;
    sX[tid] = xv;
    __syncthreads();

    int w = tid >> 5, l = tid & 31;
    int vb = blockIdx.x * 256 + w * 32;
    float2 bp = ((const float2*)b1)[l];
    float4 wA0 = sW[2 * l],      wA1 = sW[2 * l + 1];
    float4 wX0 = sW[64 + 2 * l], wX1 = sW[64 + 2 * l + 1];
    float2* H = (float2*)g_h;
    float s0 = 0.f, s1 = 0.f, q0 = 0.f, q1 = 0.f;
    int curg = -1;
    for (int vi = 0; vi < 32; vi++) {
        int vv = vb + vi;
        if (vv >= NN) break;
        int g = batch[vv];
        if (g != curg) {
            if (curg >= 0) {
                atomicAdd(&g_stats[curg * 128 + 2 * l],         s0);
                atomicAdd(&g_stats[curg * 128 + 2 * l + 1],     s1);
                atomicAdd(&g_stats[curg * 128 + 64 + 2 * l],     q0);
                atomicAdd(&g_stats[curg * 128 + 64 + 2 * l + 1], q1);
                s0 = s1 = q0 = q1 = 0.f;
            }
            curg = g;
        }
        float4 A = sA[w * 32 + vi];
        float4 X = sX[w * 32 + vi];
        float h0 = bp.x + wA0.x * A.x + wA0.y * A.y + wA0.z * A.z + wA0.w * A.w
                        + wX0.x * X.x + wX0.y * X.y + wX0.z * X.z + wX0.w * X.w;
        float h1 = bp.y + wA1.x * A.x + wA1.y * A.y + wA1.z * A.z + wA1.w * A.w
                        + wX1.x * X.x + wX1.y * X.y + wX1.z * X.z + wX1.w * X.w;
        H[vv * 32 + l] = make_float2(h0, h1);
        s0 += h0; s1 += h1; q0 += h0 * h0; q1 += h1 * h1;
    }
    if (curg >= 0) {
        atomicAdd(&g_stats[curg * 128 + 2 * l],         s0);
        atomicAdd(&g_stats[curg * 128 + 2 * l + 1],     s1);
        atomicAdd(&g_stats[curg * 128 + 64 + 2 * l],     q0);
        atomicAdd(&g_stats[curg * 128 + 64 + 2 * l + 1], q1);
    }
}

// ---------------- gather (fp16) + bias + stats: h = mean_e yl[src] + yr[v] + b --------
__global__ void __launch_bounds__(256) k_aggstats(const int* __restrict__ batch,
                                                  const float* __restrict__ bias, int so) {
    int w = threadIdx.x >> 5, l = threadIdx.x & 31;
    int vbase = blockIdx.x * 128 + w * 16;
    float2 bp = ((const float2*)bias)[l];
    const __half2* Y = (const __half2*)g_ylh;
    const float2* YR = (const float2*)g_yr;
    float2* H = (float2*)g_h;
    float* st = &g_stats[so];
    float s0 = 0.f, s1 = 0.f, q0 = 0.f, q1 = 0.f;
    int curg = -1;
    for (int vi = 0; vi < 16; vi++) {
        int v = vbase + vi;
        if (v >= NN) break;
        int g = batch[v];
        if (g != curg) {
            if (curg >= 0) {
                atomicAdd(&st[curg * 128 + 2 * l],         s0);
                atomicAdd(&st[curg * 128 + 2 * l + 1],     s1);
                atomicAdd(&st[curg * 128 + 64 + 2 * l],     q0);
                atomicAdd(&st[curg * 128 + 64 + 2 * l + 1], q1);
                s0 = s1 = q0 = q1 = 0.f;
            }
            curg = g;
        }
        int r0 = g_rowptr[v], r1 = g_rowptr[v + 1];
        float ax = 0.f, ay = 0.f;
        int e = r0;
        for (; e + 4 <= r1; e += 4) {
            int a = g_col[e], b = g_col[e + 1], c = g_col[e + 2], d = g_col[e + 3];
            float2 p0 = __half22float2(Y[a * 32 + l]);
            float2 p1 = __half22float2(Y[b * 32 + l]);
            float2 p2 = __half22float2(Y[c * 32 + l]);
            float2 p3 = __half22float2(Y[d * 32 + l]);
            ax += p0.x + p1.x + p2.x + p3.x;
            ay += p0.y + p1.y + p2.y + p3.y;
        }
        for (; e < r1; e++) {
            float2 p = __half22float2(Y[g_col[e] * 32 + l]);
            ax += p.x; ay += p.y;
        }
        float invd = 1.0f / (float)max(r1 - r0, 1);
        float2 yr = YR[v * 32 + l];
        float hx = ax * invd + yr.x + bp.x;
        float hy = ay * invd + yr.y + bp.y;
        H[v * 32 + l] = make_float2(hx, hy);
        s0 += hx; s1 += hy; q0 += hx * hx; q1 += hy * hy;
    }
    if (curg >= 0) {
        atomicAdd(&st[curg * 128 + 2 * l],         s0);
        atomicAdd(&st[curg * 128 + 2 * l + 1],     s1);
        atomicAdd(&st[curg * 128 + 64 + 2 * l],     q0);
        atomicAdd(&st[curg * 128 + 64 + 2 * l + 1], q1);
    }
}

// ---------------- fused GraphNorm(+res)+ReLU + GEMM (f32x2, duplicated A tile) --------
__global__ void __launch_bounds__(128) k_ngemm(int l3, int use_res,
        const float* __restrict__ gamma, const float* __restrict__ beta,
        const float* __restrict__ alpha, const int* __restrict__ batch, int so) {
    __shared__ float2 Asm2[64 * 65];     // A[row][k] duplicated {v,v}
    __shared__ float Wsh[16 * 128];      // quarter-K weight tile [k][n]
    __shared__ float s_am[2][64], s_sc[2][64], s_be[64];
    const float* WT = l3 ? g_WT3 : g_WT2;
    int tid = threadIdx.x;
    int n0 = blockIdx.x * 64;
    int g0 = batch[n0];
    int split = g_gstart[g0 + 1] - n0;
    int g1 = (g0 + 1 < NG) ? g0 + 1 : g0;
    {
        int side = tid >> 6, f = tid & 63;
        int g = side ? g1 : g0;
        float cnt = (float)(g_gstart[g + 1] - g_gstart[g]);
        float ic = 1.0f / cnt;
        float m   = g_stats[so + g * 128 + f] * ic;
        float ex2 = g_stats[so + g * 128 + 64 + f] * ic;
        float al = alpha[f];
        float var = ex2 - (2.0f * al - al * al) * m * m;
        s_sc[side][f] = gamma[f] * rsqrtf(var + EPSV);
        s_am[side][f] = al * m;
        if (side == 0) s_be[f] = beta[f];
    }
    __syncthreads();
    #pragma unroll
    for (int it = 0; it < 8; it++) {
        int idx = it * 512 + tid * 4;
        int row = idx >> 6, k0 = idx & 63;
        int v = n0 + row;
        float4 hv = make_float4(0.f, 0.f, 0.f, 0.f);
        float4 rv = make_float4(0.f, 0.f, 0.f, 0.f);
        if (v < NN) {
            hv = *(const float4*)&g_h[v * 64 + k0];
            if (use_res) rv = *(const float4*)&g_xc[v * 64 + k0];
        }
        int side = row >= split;
        float o[4];
        #pragma unroll
        for (int j = 0; j < 4; j++) {
            float h = (&hv.x)[j];
            float val = (h - s_am[side][k0 + j]) * s_sc[side][k0 + j] + s_be[k0 + j] + (&rv.x)[j];
            val = fmaxf(val, 0.f);
            o[j] = val;
            Asm2[row * 65 + k0 + j] = make_float2(val, val);
        }
        if (v < NN) *(float4*)&g_xc[v * 64 + k0] = *(float4*)o;
    }

    int cg = tid & 15, rg = tid >> 4;
    int c0 = cg * 8, r0 = rg * 8;
    unsigned long long acc[8][4];
    #pragma unroll
    for (int r = 0; r < 8; r++)
        #pragma unroll
        for (int j = 0; j < 4; j++) acc[r][j] = 0ull;

    for (int q = 0; q < 4; q++) {
        __syncthreads();
        #pragma unroll
        for (int i = tid * 4; i < 2048; i += 512)
            *(float4*)&Wsh[i] = *(const float4*)&WT[q * 2048 + i];
        __syncthreads();
        int kb = q * 16;
        #pragma unroll 8
        for (int k = 0; k < 16; k++) {
            const unsigned long long* wp = (const unsigned long long*)&Wsh[k * 128 + c0];
            unsigned long long w0 = wp[0], w1 = wp[1], w2 = wp[2], w3 = wp[3];
            #pragma unroll
            for (int r = 0; r < 8; r++) {
                unsigned long long a2 = *(const unsigned long long*)&Asm2[(r0 + r) * 65 + kb + k];
                asm("fma.rn.f32x2 %0, %1, %2, %0;" : "+l"(acc[r][0]) : "l"(a2), "l"(w0));
                asm("fma.rn.f32x2 %0, %1, %2, %0;" : "+l"(acc[r][1]) : "l"(a2), "l"(w1));
                asm("fma.rn.f32x2 %0, %1, %2, %0;" : "+l"(acc[r][2]) : "l"(a2), "l"(w2));
                asm("fma.rn.f32x2 %0, %1, %2, %0;" : "+l"(acc[r][3]) : "l"(a2), "l"(w3));
            }
        }
    }
    #pragma unroll
    for (int r = 0; r < 8; r++) {
        int v = n0 + r0 + r;
        if (v < NN) {
            float o[8];
            #pragma unroll
            for (int j = 0; j < 4; j++) {
                unsigned int lo, hi;
                asm("mov.b64 {%0, %1}, %2;" : "=r"(lo), "=r"(hi) : "l"(acc[r][j]));
                o[2 * j]     = __uint_as_float(lo);
                o[2 * j + 1] = __uint_as_float(hi);
            }
            if (c0 < 64) {
                __half2 hh[4];
                hh[0] = __floats2half2_rn(o[0], o[1]);
                hh[1] = __floats2half2_rn(o[2], o[3]);
                hh[2] = __floats2half2_rn(o[4], o[5]);
                hh[3] = __floats2half2_rn(o[6], o[7]);
                *(uint4*)&g_ylh[v * 64 + c0] = *(uint4*)hh;
            } else {
                int oc = c0 - 64;
                *(float4*)&g_yr[v * 64 + oc]     = *(float4*)&o[0];
                *(float4*)&g_yr[v * 64 + oc + 4] = *(float4*)&o[4];
            }
        }
    }
}

// ---------------- layer-3 norm + residual + relu fused into mean pooling --------------
__global__ void k_norm3pool(const float* __restrict__ gamma, const float* __restrict__ beta,
                            const float* __restrict__ alpha, int so) {
    int g = blockIdx.x;
    int t = threadIdx.x; // 256
    int f = t & 63, sub = t >> 6;
    int s = g_gstart[g], e = g_gstart[g + 1];
    float cnt = (float)(e - s);
    float ic = 1.0f / cnt;
    float S = g_stats[so + g * 128 + f], Q = g_stats[so + g * 128 + 64 + f];
    float al = alpha[f];
    float m = S * ic;
    float var = Q * ic - (2.0f * al - al * al) * m * m;
    float inv = rsqrtf(var + EPSV);
    float ga = gamma[f], be = beta[f], am = al * m;
    float p = 0.f;
    for (int v = s + sub; v < e; v += 4) {
        float y = ga * (g_h[v * 64 + f] - am) * inv + be + g_xc[v * 64 + f];
        p += fmaxf(y, 0.f);
    }
    __shared__ float sh[256];
    sh[t] = p;
    __syncthreads();
    if (sub == 0) {
        p = sh[t] + sh[t + 64] + sh[t + 128] + sh[t + 192];
        g_pooled[g * 64 + f] = p * ic;
    }
}

// ---------------- final linear head ----------------
__global__ void k_final(const float* __restrict__ Wlin, const float* __restrict__ blin,
                        float* __restrict__ out) {
    int g = threadIdx.x; // 128
    float s0 = 0.f, s1 = 0.f, s2 = 0.f;
    #pragma unroll 8
    for (int f = 0; f < 64; f++) {
        float pv = g_pooled[g * 64 + f];
        s0 += pv * Wlin[f];
        s1 += pv * Wlin[64 + f];
        s2 += pv * Wlin[128 + f];
    }
    out[g * 3 + 0] = s0 + blin[0];
    out[g * 3 + 1] = s1 + blin[1];
    out[g * 3 + 2] = s2 + blin[2];
}

// ---------------- launch ----------------
extern "C" void kernel_launch(void* const* d_in, const int* in_sizes, int n_in,
                              void* d_out, int out_size) {
    const float* x     = (const float*)d_in[0];
    const int*   ei    = (const int*)d_in[1];
    const int*   batch = (const int*)d_in[2];
    const float* W1l = (const float*)d_in[3];
    const float* b1  = (const float*)d_in[4];
    const float* W1r = (const float*)d_in[5];
    const float* W2l = (const float*)d_in[6];
    const float* b2  = (const float*)d_in[7];
    const float* W2r = (const float*)d_in[8];
    const float* W3l = (const float*)d_in[9];
    const float* b3  = (const float*)d_in[10];
    const float* W3r = (const float*)d_in[11];
    const float* g1  = (const float*)d_in[12];
    const float* be1 = (const float*)d_in[13];
    const float* a1  = (const float*)d_in[14];
    const float* g2  = (const float*)d_in[15];
    const float* be2 = (const float*)d_in[16];
    const float* a2  = (const float*)d_in[17];
    const float* g3  = (const float*)d_in[18];
    const float* be3 = (const float*)d_in[19];
    const float* a3  = (const float*)d_in[20];
    const float* Wlin = (const float*)d_in[21];
    const float* blin = (const float*)d_in[22];
    float* out = (float*)d_out;

    k_prep<<<(NN + 255) / 256, 256>>>(batch, W1l, W1r, W2l, W2r, W3l, W3r);
    k_hist<<<(NE + 255) / 256, 256>>>(ei);
    k_scan1<<<NSC, 1024>>>();
    k_scan2<<<1, 128>>>();
    k_scan3<<<NSC, 1024>>>();
    k_scatter<<<(NE + 255) / 256, 256>>>(ei);

    const int AGG_BLOCKS = (NN + 127) / 128;
    const int GEMM_BLOCKS = (NN + 63) / 64;

    // layer 1 (fused gather-x + K=4 GEMM + stats)
    k_layer1<<<(NN + 255) / 256, 256>>>(x, b1, batch);
    // layer 2 (norm1 fused into GEMM)
    k_ngemm<<<GEMM_BLOCKS, 128>>>(0, 0, g1, be1, a1, batch, 0);
    k_aggstats<<<AGG_BLOCKS, 256>>>(batch, b2, NG * 128);
    // layer 3 (norm2 + residual fused into GEMM)
    k_ngemm<<<GEMM_BLOCKS, 128>>>(1, 1, g2, be2, a2, batch, NG * 128);
    k_aggstats<<<AGG_BLOCKS, 256>>>(batch, b3, 2 * NG * 128);

    k_norm3pool<<<NG, 256>>>(g3, be3, a3, 2 * NG * 128);
    k_final<<<1, 128>>>(Wlin, blin, out);
}

// round 5
// speedup vs baseline: 2.1693x; 1.3186x over previous
#include <cuda_runtime.h>
#include <cuda_bf16.h>
#include <cuda_fp16.h>

#define NN 100000
#define NE 1200000
#define NG 128
#define HIDN 64
#define EPSV 1e-5f
#define NSC ((NN + 1023) / 1024)   // 98 scan blocks

// ---------------- scratch ----------------
__device__ int    g_deg[NN];
__device__ int    g_rowptr[NN + 1];
__device__ int    g_wp[NN];
__device__ int    g_col[NE];
__device__ int    g_gstart[NG + 1];
__device__ int    g_bsum[NSC];
__device__ __half g_ylh[NN * 64];        // GEMM left output (gathered), fp16
__device__ float  g_yr[NN * 64];         // GEMM right output (self), fp32
__device__ float  g_h[NN * HIDN];        // conv output (pre-norm)
__device__ float  g_xc[NN * HIDN];       // normalized activations (x1 / x2)
__device__ float  g_stats[3 * NG * 128]; // per layer, per graph: [sum(64) | sumsq(64)]
__device__ float  g_pooled[NG * HIDN];
__device__ float  g_WT1[128 * 4];        // [n][k]  (n: 0..63 -> W1l, 64..127 -> W1r)
// split-fp16 weights, [n][k] layout, 32 words (half2) per row, XOR-swizzled:
//   word index stored at  n*32 + (w ^ ((n&7)<<2))
__device__ unsigned int g_W2hi[4096], g_W2lo[4096];
__device__ unsigned int g_W3hi[4096], g_W3lo[4096];

// ---------------- merged prep: zero + gstart + weight prep ----------------
__global__ void k_prep(const int* __restrict__ batch,
                       const float* __restrict__ W1l, const float* __restrict__ W1r,
                       const float* __restrict__ W2l, const float* __restrict__ W2r,
                       const float* __restrict__ W3l, const float* __restrict__ W3r) {
    int i = blockIdx.x * blockDim.x + threadIdx.x;
    if (i < NN) {
        g_deg[i] = 0;
        int b = batch[i];
        if (i == 0 || batch[i - 1] != b) g_gstart[b] = i;
    }
    if (i == 0) g_gstart[NG] = NN;
    if (i < 3 * NG * 128) g_stats[i] = 0.f;
    if (i < 512) {
        int n = i >> 2, k = i & 3;
        g_WT1[n * 4 + k] = (n < 64) ? W1l[n * 4 + k] : W1r[(n - 64) * 4 + k];
    }
    if (i < 4096) {
        int n = i >> 5, w = i & 31;
        int k0 = w * 2;
        int sw = n * 32 + (w ^ ((n & 7) << 2));
        // layer 2
        float w0 = (n < 64) ? W2l[n * 64 + k0]     : W2r[(n - 64) * 64 + k0];
        float w1 = (n < 64) ? W2l[n * 64 + k0 + 1] : W2r[(n - 64) * 64 + k0 + 1];
        __half h0 = __float2half_rn(w0), h1 = __float2half_rn(w1);
        __half l0 = __float2half_rn(w0 - __half2float(h0));
        __half l1 = __float2half_rn(w1 - __half2float(h1));
        __half2 hh = __halves2half2(h0, h1), ll = __halves2half2(l0, l1);
        g_W2hi[sw] = *(unsigned int*)&hh;
        g_W2lo[sw] = *(unsigned int*)&ll;
        // layer 3
        w0 = (n < 64) ? W3l[n * 64 + k0]     : W3r[(n - 64) * 64 + k0];
        w1 = (n < 64) ? W3l[n * 64 + k0 + 1] : W3r[(n - 64) * 64 + k0 + 1];
        h0 = __float2half_rn(w0); h1 = __float2half_rn(w1);
        l0 = __float2half_rn(w0 - __half2float(h0));
        l1 = __float2half_rn(w1 - __half2float(h1));
        hh = __halves2half2(h0, h1); ll = __halves2half2(l0, l1);
        g_W3hi[sw] = *(unsigned int*)&hh;
        g_W3lo[sw] = *(unsigned int*)&ll;
    }
}

__global__ void k_hist(const int* __restrict__ ei) {
    int e = blockIdx.x * blockDim.x + threadIdx.x;
    if (e < NE) atomicAdd(&g_deg[ei[NE + e]], 1);
}

// ---------------- parallel 2-phase scan ----------------
__global__ void k_scan1() {
    __shared__ int ws[32];
    int b = blockIdx.x, t = threadIdx.x, lane = t & 31, w = t >> 5;
    int i = b * 1024 + t;
    int v = (i < NN) ? g_deg[i] : 0;
    #pragma unroll
    for (int o = 16; o >= 1; o >>= 1) v += __shfl_xor_sync(0xFFFFFFFFu, v, o);
    if (lane == 0) ws[w] = v;
    __syncthreads();
    if (t < 32) {
        int s = ws[t];
        #pragma unroll
        for (int o = 16; o >= 1; o >>= 1) s += __shfl_xor_sync(0xFFFFFFFFu, s, o);
        if (t == 0) g_bsum[b] = s;
    }
}

__global__ void k_scan3() {
    __shared__ int warpsum[32];
    __shared__ int offs[4];
    __shared__ int s_off;
    int b = blockIdx.x, t = threadIdx.x, lane = t & 31, w = t >> 5;
    // block offset = sum of bsum[0..b)
    if (t < 128) {
        int val = (t < b && t < NSC) ? g_bsum[t] : 0;
        #pragma unroll
        for (int o = 16; o >= 1; o >>= 1) val += __shfl_xor_sync(0xFFFFFFFFu, val, o);
        if (lane == 0) offs[t >> 5] = val;
    }
    __syncthreads();
    if (t == 0) s_off = offs[0] + offs[1] + offs[2] + offs[3];
    int i = b * 1024 + t;
    int d = (i < NN) ? g_deg[i] : 0;
    int v = d;
    #pragma unroll
    for (int o = 1; o < 32; o <<= 1) {
        int n = __shfl_up_sync(0xFFFFFFFFu, v, o);
        if (lane >= o) v += n;
    }
    if (lane == 31) warpsum[w] = v;
    __syncthreads();
    if (w == 0) {
        int s = warpsum[lane];
        #pragma unroll
        for (int o = 1; o < 32; o <<= 1) {
            int n = __shfl_up_sync(0xFFFFFFFFu, s, o);
            if (lane >= o) s += n;
        }
        warpsum[lane] = s;
    }
    __syncthreads();
    int ex = s_off + v - d + (w > 0 ? warpsum[w - 1] : 0);
    if (i < NN) { g_rowptr[i] = ex; g_wp[i] = ex; }
    if (i == NN - 1) g_rowptr[NN] = ex + d;
}

__global__ void k_scatter(const int* __restrict__ ei) {
    int e = blockIdx.x * blockDim.x + threadIdx.x;
    if (e < NE) {
        int src = ei[e];
        int dst = ei[NE + e];
        int p = atomicAdd(&g_wp[dst], 1);
        g_col[p] = src;
    }
}

// ---------------- layer 1 fully fused: gather x (16B/edge) + K=4 GEMM + stats ----------
__global__ void __launch_bounds__(256) k_layer1(const float* __restrict__ x,
                                                const float* __restrict__ b1,
                                                const int* __restrict__ batch) {
    __shared__ float4 sA[256], sX[256];
    __shared__ float4 sW[128];
    int tid = threadIdx.x;
    if (tid < 128) sW[tid] = ((const float4*)g_WT1)[tid];
    int v = blockIdx.x * 256 + tid;
    float4 agg = make_float4(0.f, 0.f, 0.f, 0.f);
    float4 xv  = make_float4(0.f, 0.f, 0.f, 0.f);
    if (v < NN) {
        int r0 = g_rowptr[v], r1 = g_rowptr[v + 1];
        const float4* X4 = (const float4*)x;
        float4 a0 = agg, a1 = agg, a2 = agg, a3 = agg;
        int e = r0;
        for (; e + 4 <= r1; e += 4) {
            float4 p0 = X4[g_col[e]];
            float4 p1 = X4[g_col[e + 1]];
            float4 p2 = X4[g_col[e + 2]];
            float4 p3 = X4[g_col[e + 3]];
            a0.x += p0.x; a0.y += p0.y; a0.z += p0.z; a0.w += p0.w;
            a1.x += p1.x; a1.y += p1.y; a1.z += p1.z; a1.w += p1.w;
            a2.x += p2.x; a2.y += p2.y; a2.z += p2.z; a2.w += p2.w;
            a3.x += p3.x; a3.y += p3.y; a3.z += p3.z; a3.w += p3.w;
        }
        for (; e < r1; e++) {
            float4 p = X4[g_col[e]];
            a0.x += p.x; a0.y += p.y; a0.z += p.z; a0.w += p.w;
        }
        float invd = 1.0f / (float)max(r1 - r0, 1);
        agg.x = (a0.x + a1.x + a2.x + a3.x) * invd;
        agg.y = (a0.y + a1.y + a2.y + a3.y) * invd;
        agg.z = (a0.z + a1.z + a2.z + a3.z) * invd;
        agg.w = (a0.w + a1.w + a2.w + a3.w) * invd;
        xv = X4[v];
    }
    sA[tid] = agg;
    sX[tid] = xv;
    __syncthreads();

    int w = tid >> 5, l = tid & 31;
    int vb = blockIdx.x * 256 + w * 32;
    float2 bp = ((const float2*)b1)[l];
    float4 wA0 = sW[2 * l],      wA1 = sW[2 * l + 1];
    float4 wX0 = sW[64 + 2 * l], wX1 = sW[64 + 2 * l + 1];
    float2* H = (float2*)g_h;
    float s0 = 0.f, s1 = 0.f, q0 = 0.f, q1 = 0.f;
    int curg = -1;
    for (int vi = 0; vi < 32; vi++) {
        int vv = vb + vi;
        if (vv >= NN) break;
        int g = batch[vv];
        if (g != curg) {
            if (curg >= 0) {
                atomicAdd(&g_stats[curg * 128 + 2 * l],         s0);
                atomicAdd(&g_stats[curg * 128 + 2 * l + 1],     s1);
                atomicAdd(&g_stats[curg * 128 + 64 + 2 * l],     q0);
                atomicAdd(&g_stats[curg * 128 + 64 + 2 * l + 1], q1);
                s0 = s1 = q0 = q1 = 0.f;
            }
            curg = g;
        }
        float4 A = sA[w * 32 + vi];
        float4 X = sX[w * 32 + vi];
        float h0 = bp.x + wA0.x * A.x + wA0.y * A.y + wA0.z * A.z + wA0.w * A.w
                        + wX0.x * X.x + wX0.y * X.y + wX0.z * X.z + wX0.w * X.w;
        float h1 = bp.y + wA1.x * A.x + wA1.y * A.y + wA1.z * A.z + wA1.w * A.w
                        + wX1.x * X.x + wX1.y * X.y + wX1.z * X.z + wX1.w * X.w;
        H[vv * 32 + l] = make_float2(h0, h1);
        s0 += h0; s1 += h1; q0 += h0 * h0; q1 += h1 * h1;
    }
    if (curg >= 0) {
        atomicAdd(&g_stats[curg * 128 + 2 * l],         s0);
        atomicAdd(&g_stats[curg * 128 + 2 * l + 1],     s1);
        atomicAdd(&g_stats[curg * 128 + 64 + 2 * l],     q0);
        atomicAdd(&g_stats[curg * 128 + 64 + 2 * l + 1], q1);
    }
}

// ---------------- gather (fp16) + bias + stats: h = mean_e yl[src] + yr[v] + b --------
__global__ void __launch_bounds__(256) k_aggstats(const int* __restrict__ batch,
                                                  const float* __restrict__ bias, int so) {
    int w = threadIdx.x >> 5, l = threadIdx.x & 31;
    int vbase = blockIdx.x * 128 + w * 16;
    float2 bp = ((const float2*)bias)[l];
    const __half2* Y = (const __half2*)g_ylh;
    const float2* YR = (const float2*)g_yr;
    float2* H = (float2*)g_h;
    float* st = &g_stats[so];
    float s0 = 0.f, s1 = 0.f, q0 = 0.f, q1 = 0.f;
    int curg = -1;
    for (int vi = 0; vi < 16; vi++) {
        int v = vbase + vi;
        if (v >= NN) break;
        int g = batch[v];
        if (g != curg) {
            if (curg >= 0) {
                atomicAdd(&st[curg * 128 + 2 * l],         s0);
                atomicAdd(&st[curg * 128 + 2 * l + 1],     s1);
                atomicAdd(&st[curg * 128 + 64 + 2 * l],     q0);
                atomicAdd(&st[curg * 128 + 64 + 2 * l + 1], q1);
                s0 = s1 = q0 = q1 = 0.f;
            }
            curg = g;
        }
        int r0 = g_rowptr[v], r1 = g_rowptr[v + 1];
        float ax = 0.f, ay = 0.f;
        int e = r0;
        for (; e + 4 <= r1; e += 4) {
            int a = g_col[e], b = g_col[e + 1], c = g_col[e + 2], d = g_col[e + 3];
            float2 p0 = __half22float2(Y[a * 32 + l]);
            float2 p1 = __half22float2(Y[b * 32 + l]);
            float2 p2 = __half22float2(Y[c * 32 + l]);
            float2 p3 = __half22float2(Y[d * 32 + l]);
            ax += p0.x + p1.x + p2.x + p3.x;
            ay += p0.y + p1.y + p2.y + p3.y;
        }
        for (; e < r1; e++) {
            float2 p = __half22float2(Y[g_col[e] * 32 + l]);
            ax += p.x; ay += p.y;
        }
        float invd = 1.0f / (float)max(r1 - r0, 1);
        float2 yr = YR[v * 32 + l];
        float hx = ax * invd + yr.x + bp.x;
        float hy = ay * invd + yr.y + bp.y;
        H[v * 32 + l] = make_float2(hx, hy);
        s0 += hx; s1 += hy; q0 += hx * hx; q1 += hy * hy;
    }
    if (curg >= 0) {
        atomicAdd(&st[curg * 128 + 2 * l],         s0);
        atomicAdd(&st[curg * 128 + 2 * l + 1],     s1);
        atomicAdd(&st[curg * 128 + 64 + 2 * l],     q0);
        atomicAdd(&st[curg * 128 + 64 + 2 * l + 1], q1);
    }
}

#define MMA16816(ac, A0, A1, A2, A3, B0, B1)                                  \
    asm volatile("mma.sync.aligned.m16n8k16.row.col.f32.f16.f16.f32 "         \
                 "{%0,%1,%2,%3}, {%4,%5,%6,%7}, {%8,%9}, {%0,%1,%2,%3};"      \
                 : "+f"(ac[0]), "+f"(ac[1]), "+f"(ac[2]), "+f"(ac[3])         \
                 : "r"(A0), "r"(A1), "r"(A2), "r"(A3), "r"(B0), "r"(B1))

// ---------------- fused GraphNorm(+res)+ReLU + tensor-core GEMM ----------------------
// block: 64 rows x 128 cols, 128 threads (4 warps, 16 rows each), mma.m16n8k16
// weights split fp16 hi+lo (two MMAs -> effectively exact weights)
__global__ void __launch_bounds__(128) k_ngemm(int l3, int use_res,
        const float* __restrict__ gamma, const float* __restrict__ beta,
        const float* __restrict__ alpha, const int* __restrict__ batch, int so) {
    __shared__ unsigned int Ah[64 * 32];     // A fp16 [row][word], XOR-swizzled
    __shared__ unsigned int Whi[4096];       // [n][word] swizzled (verbatim copy)
    __shared__ unsigned int Wlo[4096];
    __shared__ float s_am[2][64], s_sc[2][64], s_be[64];
    const unsigned int* GWhi = l3 ? g_W3hi : g_W2hi;
    const unsigned int* GWlo = l3 ? g_W3lo : g_W2lo;
    int tid = threadIdx.x;
    int n0 = blockIdx.x * 64;

    // W tiles -> smem (vectorized)
    #pragma unroll
    for (int i = tid; i < 1024; i += 128) {
        ((uint4*)Whi)[i] = ((const uint4*)GWhi)[i];
        ((uint4*)Wlo)[i] = ((const uint4*)GWlo)[i];
    }

    int g0 = batch[n0];
    int split = g_gstart[g0 + 1] - n0;
    int g1 = (g0 + 1 < NG) ? g0 + 1 : g0;
    {
        int side = tid >> 6, f = tid & 63;
        int g = side ? g1 : g0;
        float cnt = (float)(g_gstart[g + 1] - g_gstart[g]);
        float ic = 1.0f / cnt;
        float m   = g_stats[so + g * 128 + f] * ic;
        float ex2 = g_stats[so + g * 128 + 64 + f] * ic;
        float al = alpha[f];
        float var = ex2 - (2.0f * al - al * al) * m * m;
        s_sc[side][f] = gamma[f] * rsqrtf(var + EPSV);
        s_am[side][f] = al * m;
        if (side == 0) s_be[f] = beta[f];
    }
    __syncthreads();
    // norm (+res) + relu -> fp16 A tile (swizzled) + fp32 g_xc
    #pragma unroll
    for (int it = 0; it < 8; it++) {
        int idx = it * 512 + tid * 4;
        int row = idx >> 6, k0 = idx & 63;
        int v = n0 + row;
        float4 hv = make_float4(0.f, 0.f, 0.f, 0.f);
        float4 rv = make_float4(0.f, 0.f, 0.f, 0.f);
        if (v < NN) {
            hv = *(const float4*)&g_h[v * 64 + k0];
            if (use_res) rv = *(const float4*)&g_xc[v * 64 + k0];
        }
        int side = row >= split;
        float o[4];
        #pragma unroll
        for (int j = 0; j < 4; j++) {
            float h = (&hv.x)[j];
            float val = (h - s_am[side][k0 + j]) * s_sc[side][k0 + j] + s_be[k0 + j] + (&rv.x)[j];
            val = fmaxf(val, 0.f);
            o[j] = val;
        }
        int w0 = k0 >> 1;                 // even
        int mask = (row & 7) << 2;
        __half2 p0 = __floats2half2_rn(o[0], o[1]);
        __half2 p1 = __floats2half2_rn(o[2], o[3]);
        Ah[row * 32 + (w0 ^ mask)]       = *(unsigned int*)&p0;
        Ah[row * 32 + ((w0 + 1) ^ mask)] = *(unsigned int*)&p1;
        if (v < NN) *(float4*)&g_xc[v * 64 + k0] = *(float4*)o;
    }
    __syncthreads();

    int lane = tid & 31, wid = tid >> 5;
    int grp = lane >> 2, qid = lane & 3;
    int mbase = wid * 16;
    int rowA = mbase + grp;                  // rowA & 7 == grp
    int maskA = grp << 2;
    float acc[16][4];
    #pragma unroll
    for (int j = 0; j < 16; j++)
        #pragma unroll
        for (int c = 0; c < 4; c++) acc[j][c] = 0.f;

    #pragma unroll
    for (int ks = 0; ks < 4; ks++) {
        int wa = ks * 8 + qid;
        unsigned int a0 = Ah[rowA * 32 + (wa ^ maskA)];
        unsigned int a1 = Ah[(rowA + 8) * 32 + (wa ^ maskA)];
        unsigned int a2 = Ah[rowA * 32 + ((wa + 4) ^ maskA)];
        unsigned int a3 = Ah[(rowA + 8) * 32 + ((wa + 4) ^ maskA)];
        #pragma unroll
        for (int j = 0; j < 16; j++) {
            int n = j * 8 + grp;
            unsigned int b0 = Whi[n * 32 + (wa ^ maskA)];
            unsigned int b1 = Whi[n * 32 + ((wa + 4) ^ maskA)];
            MMA16816(acc[j], a0, a1, a2, a3, b0, b1);
            unsigned int c0 = Wlo[n * 32 + (wa ^ maskA)];
            unsigned int c1 = Wlo[n * 32 + ((wa + 4) ^ maskA)];
            MMA16816(acc[j], a0, a1, a2, a3, c0, c1);
        }
    }

    // epilogue: n-tiles 0..7 -> g_ylh (fp16), 8..15 -> g_yr (fp32)
    int v0 = n0 + mbase + grp;
    int v1 = v0 + 8;
    #pragma unroll
    for (int j = 0; j < 16; j++) {
        int n = j * 8 + qid * 2;
        if (j < 8) {
            __half2 d01 = __floats2half2_rn(acc[j][0], acc[j][1]);
            __half2 d23 = __floats2half2_rn(acc[j][2], acc[j][3]);
            if (v0 < NN) *(__half2*)&g_ylh[v0 * 64 + n] = d01;
            if (v1 < NN) *(__half2*)&g_ylh[v1 * 64 + n] = d23;
        } else {
            int nn = n - 64;
            if (v0 < NN) *(float2*)&g_yr[v0 * 64 + nn] = make_float2(acc[j][0], acc[j][1]);
            if (v1 < NN) *(float2*)&g_yr[v1 * 64 + nn] = make_float2(acc[j][2], acc[j][3]);
        }
    }
}

// ---------------- layer-3 norm + residual + relu + mean pool + linear head -----------
__global__ void k_norm3pool(const float* __restrict__ gamma, const float* __restrict__ beta,
                            const float* __restrict__ alpha, int so,
                            const float* __restrict__ Wlin, const float* __restrict__ blin,
                            float* __restrict__ out) {
    int g = blockIdx.x;
    int t = threadIdx.x; // 256
    int f = t & 63, sub = t >> 6;
    int s = g_gstart[g], e = g_gstart[g + 1];
    float cnt = (float)(e - s);
    float ic = 1.0f / cnt;
    float S = g_stats[so + g * 128 + f], Q = g_stats[so + g * 128 + 64 + f];
    float al = alpha[f];
    float m = S * ic;
    float var = Q * ic - (2.0f * al - al * al) * m * m;
    float inv = rsqrtf(var + EPSV);
    float ga = gamma[f], be = beta[f], am = al * m;
    float p = 0.f;
    for (int v = s + sub; v < e; v += 4) {
        float y = ga * (g_h[v * 64 + f] - am) * inv + be + g_xc[v * 64 + f];
        p += fmaxf(y, 0.f);
    }
    __shared__ float sh[256];
    __shared__ float pool[64];
    sh[t] = p;
    __syncthreads();
    if (sub == 0) {
        p = (sh[t] + sh[t + 64] + sh[t + 128] + sh[t + 192]) * ic;
        g_pooled[g * 64 + f] = p;
        pool[f] = p;
    }
    __syncthreads();
    if (t < 3) {
        float s0 = blin[t];
        #pragma unroll 8
        for (int ff = 0; ff < 64; ff++) s0 += pool[ff] * Wlin[t * 64 + ff];
        out[g * 3 + t] = s0;
    }
}

// ---------------- launch ----------------
extern "C" void kernel_launch(void* const* d_in, const int* in_sizes, int n_in,
                              void* d_out, int out_size) {
    const float* x     = (const float*)d_in[0];
    const int*   ei    = (const int*)d_in[1];
    const int*   batch = (const int*)d_in[2];
    const float* W1l = (const float*)d_in[3];
    const float* b1  = (const float*)d_in[4];
    const float* W1r = (const float*)d_in[5];
    const float* W2l = (const float*)d_in[6];
    const float* b2  = (const float*)d_in[7];
    const float* W2r = (const float*)d_in[8];
    const float* W3l = (const float*)d_in[9];
    const float* b3  = (const float*)d_in[10];
    const float* W3r = (const float*)d_in[11];
    const float* g1  = (const float*)d_in[12];
    const float* be1 = (const float*)d_in[13];
    const float* a1  = (const float*)d_in[14];
    const float* g2  = (const float*)d_in[15];
    const float* be2 = (const float*)d_in[16];
    const float* a2  = (const float*)d_in[17];
    const float* g3  = (const float*)d_in[18];
    const float* be3 = (const float*)d_in[19];
    const float* a3  = (const float*)d_in[20];
    const float* Wlin = (const float*)d_in[21];
    const float* blin = (const float*)d_in[22];
    float* out = (float*)d_out;

    k_prep<<<(NN + 255) / 256, 256>>>(batch, W1l, W1r, W2l, W2r, W3l, W3r);
    k_hist<<<(NE + 255) / 256, 256>>>(ei);
    k_scan1<<<NSC, 1024>>>();
    k_scan3<<<NSC, 1024>>>();
    k_scatter<<<(NE + 255) / 256, 256>>>(ei);

    const int AGG_BLOCKS = (NN + 127) / 128;
    const int GEMM_BLOCKS = (NN + 63) / 64;

    // layer 1 (fused gather-x + K=4 GEMM + stats)
    k_layer1<<<(NN + 255) / 256, 256>>>(x, b1, batch);
    // layer 2 (norm1 fused into GEMM)
    k_ngemm<<<GEMM_BLOCKS, 128>>>(0, 0, g1, be1, a1, batch, 0);
    k_aggstats<<<AGG_BLOCKS, 256>>>(batch, b2, NG * 128);
    // layer 3 (norm2 + residual fused into GEMM)
    k_ngemm<<<GEMM_BLOCKS, 128>>>(1, 1, g2, be2, a2, batch, NG * 128);
    k_aggstats<<<AGG_BLOCKS, 256>>>(batch, b3, 2 * NG * 128);

    // norm3 + residual + relu + mean pool + head
    k_norm3pool<<<NG, 256>>>(g3, be3, a3, 2 * NG * 128, Wlin, blin, out);
}

// round 6
// speedup vs baseline: 2.5826x; 1.1905x over previous
#include <cuda_runtime.h>
#include <cuda_bf16.h>
#include <cuda_fp16.h>

#define NN 100000
#define NE 1200000
#define NG 128
#define HIDN 64
#define EPSV 1e-5f
#define NSC ((NN + 1023) / 1024)   // 98 scan blocks

// ---------------- scratch ----------------
__device__ int    g_deg[NN];
__device__ int    g_rowptr[NN + 1];
__device__ int    g_wp[NN];
__device__ int    g_col[NE];
__device__ int    g_gstart[NG + 1];
__device__ int    g_bsum[NSC];
__device__ __half g_ylh[NN * 64];        // GEMM left output (gathered), fp16
__device__ __half g_yr[NN * 64];         // GEMM right output (self), fp16
__device__ __half g_h[NN * HIDN];        // conv output (pre-norm), fp16
__device__ __half g_xc[NN * HIDN];       // normalized activations (x1 / x2), fp16
__device__ float  g_stats[3 * NG * 128]; // per layer, per graph: [sum(64) | sumsq(64)]
__device__ float  g_pooled[NG * HIDN];
__device__ float  g_WT1[128 * 4];        // [n][k]  (n: 0..63 -> W1l, 64..127 -> W1r)
// split-fp16 weights, [n][k] layout, 32 words (half2) per row, XOR-swizzled:
//   word index stored at  n*32 + (w ^ ((n&7)<<2))
__device__ unsigned int g_W2hi[4096], g_W2lo[4096];
__device__ unsigned int g_W3hi[4096], g_W3lo[4096];

// ---------------- merged prep: zero + gstart + weight prep ----------------
__global__ void k_prep(const int* __restrict__ batch,
                       const float* __restrict__ W1l, const float* __restrict__ W1r,
                       const float* __restrict__ W2l, const float* __restrict__ W2r,
                       const float* __restrict__ W3l, const float* __restrict__ W3r) {
    int i = blockIdx.x * blockDim.x + threadIdx.x;
    if (i < NN) {
        g_deg[i] = 0;
        int b = batch[i];
        if (i == 0 || batch[i - 1] != b) g_gstart[b] = i;
    }
    if (i == 0) g_gstart[NG] = NN;
    if (i < 3 * NG * 128) g_stats[i] = 0.f;
    if (i < 512) {
        int n = i >> 2, k = i & 3;
        g_WT1[n * 4 + k] = (n < 64) ? W1l[n * 4 + k] : W1r[(n - 64) * 4 + k];
    }
    if (i < 4096) {
        int n = i >> 5, w = i & 31;
        int k0 = w * 2;
        int sw = n * 32 + (w ^ ((n & 7) << 2));
        // layer 2
        float w0 = (n < 64) ? W2l[n * 64 + k0]     : W2r[(n - 64) * 64 + k0];
        float w1 = (n < 64) ? W2l[n * 64 + k0 + 1] : W2r[(n - 64) * 64 + k0 + 1];
        __half h0 = __float2half_rn(w0), h1 = __float2half_rn(w1);
        __half l0 = __float2half_rn(w0 - __half2float(h0));
        __half l1 = __float2half_rn(w1 - __half2float(h1));
        __half2 hh = __halves2half2(h0, h1), ll = __halves2half2(l0, l1);
        g_W2hi[sw] = *(unsigned int*)&hh;
        g_W2lo[sw] = *(unsigned int*)&ll;
        // layer 3
        w0 = (n < 64) ? W3l[n * 64 + k0]     : W3r[(n - 64) * 64 + k0];
        w1 = (n < 64) ? W3l[n * 64 + k0 + 1] : W3r[(n - 64) * 64 + k0 + 1];
        h0 = __float2half_rn(w0); h1 = __float2half_rn(w1);
        l0 = __float2half_rn(w0 - __half2float(h0));
        l1 = __float2half_rn(w1 - __half2float(h1));
        hh = __halves2half2(h0, h1); ll = __halves2half2(l0, l1);
        g_W3hi[sw] = *(unsigned int*)&hh;
        g_W3lo[sw] = *(unsigned int*)&ll;
    }
}

__global__ void k_hist(const int* __restrict__ ei) {
    int e = blockIdx.x * blockDim.x + threadIdx.x;
    if (e < NE) atomicAdd(&g_deg[ei[NE + e]], 1);
}

// ---------------- parallel 2-phase scan ----------------
__global__ void k_scan1() {
    __shared__ int ws[32];
    int b = blockIdx.x, t = threadIdx.x, lane = t & 31, w = t >> 5;
    int i = b * 1024 + t;
    int v = (i < NN) ? g_deg[i] : 0;
    #pragma unroll
    for (int o = 16; o >= 1; o >>= 1) v += __shfl_xor_sync(0xFFFFFFFFu, v, o);
    if (lane == 0) ws[w] = v;
    __syncthreads();
    if (t < 32) {
        int s = ws[t];
        #pragma unroll
        for (int o = 16; o >= 1; o >>= 1) s += __shfl_xor_sync(0xFFFFFFFFu, s, o);
        if (t == 0) g_bsum[b] = s;
    }
}

__global__ void k_scan3() {
    __shared__ int warpsum[32];
    __shared__ int offs[4];
    __shared__ int s_off;
    int b = blockIdx.x, t = threadIdx.x, lane = t & 31, w = t >> 5;
    if (t < 128) {
        int val = (t < b && t < NSC) ? g_bsum[t] : 0;
        #pragma unroll
        for (int o = 16; o >= 1; o >>= 1) val += __shfl_xor_sync(0xFFFFFFFFu, val, o);
        if (lane == 0) offs[t >> 5] = val;
    }
    __syncthreads();
    if (t == 0) s_off = offs[0] + offs[1] + offs[2] + offs[3];
    int i = b * 1024 + t;
    int d = (i < NN) ? g_deg[i] : 0;
    int v = d;
    #pragma unroll
    for (int o = 1; o < 32; o <<= 1) {
        int n = __shfl_up_sync(0xFFFFFFFFu, v, o);
        if (lane >= o) v += n;
    }
    if (lane == 31) warpsum[w] = v;
    __syncthreads();
    if (w == 0) {
        int s = warpsum[lane];
        #pragma unroll
        for (int o = 1; o < 32; o <<= 1) {
            int n = __shfl_up_sync(0xFFFFFFFFu, s, o);
            if (lane >= o) s += n;
        }
        warpsum[lane] = s;
    }
    __syncthreads();
    int ex = s_off + v - d + (w > 0 ? warpsum[w - 1] : 0);
    if (i < NN) { g_rowptr[i] = ex; g_wp[i] = ex; }
    if (i == NN - 1) g_rowptr[NN] = ex + d;
}

__global__ void k_scatter(const int* __restrict__ ei) {
    int e = blockIdx.x * blockDim.x + threadIdx.x;
    if (e < NE) {
        int src = ei[e];
        int dst = ei[NE + e];
        int p = atomicAdd(&g_wp[dst], 1);
        g_col[p] = src;
    }
}

// ---------------- layer 1 fully fused: gather x (16B/edge) + K=4 GEMM + stats ----------
__global__ void __launch_bounds__(256) k_layer1(const float* __restrict__ x,
                                                const float* __restrict__ b1,
                                                const int* __restrict__ batch) {
    __shared__ float4 sA[256], sX[256];
    __shared__ float4 sW[128];
    int tid = threadIdx.x;
    if (tid < 128) sW[tid] = ((const float4*)g_WT1)[tid];
    int v = blockIdx.x * 256 + tid;
    float4 agg = make_float4(0.f, 0.f, 0.f, 0.f);
    float4 xv  = make_float4(0.f, 0.f, 0.f, 0.f);
    if (v < NN) {
        int r0 = g_rowptr[v], r1 = g_rowptr[v + 1];
        const float4* X4 = (const float4*)x;
        float4 a0 = agg, a1 = agg, a2 = agg, a3 = agg;
        int e = r0;
        for (; e + 4 <= r1; e += 4) {
            float4 p0 = X4[g_col[e]];
            float4 p1 = X4[g_col[e + 1]];
            float4 p2 = X4[g_col[e + 2]];
            float4 p3 = X4[g_col[e + 3]];
            a0.x += p0.x; a0.y += p0.y; a0.z += p0.z; a0.w += p0.w;
            a1.x += p1.x; a1.y += p1.y; a1.z += p1.z; a1.w += p1.w;
            a2.x += p2.x; a2.y += p2.y; a2.z += p2.z; a2.w += p2.w;
            a3.x += p3.x; a3.y += p3.y; a3.z += p3.z; a3.w += p3.w;
        }
        for (; e < r1; e++) {
            float4 p = X4[g_col[e]];
            a0.x += p.x; a0.y += p.y; a0.z += p.z; a0.w += p.w;
        }
        float invd = 1.0f / (float)max(r1 - r0, 1);
        agg.x = (a0.x + a1.x + a2.x + a3.x) * invd;
        agg.y = (a0.y + a1.y + a2.y + a3.y) * invd;
        agg.z = (a0.z + a1.z + a2.z + a3.z) * invd;
        agg.w = (a0.w + a1.w + a2.w + a3.w) * invd;
        xv = X4[v];
    }
    sA[tid] = agg;
    sX[tid] = xv;
    __syncthreads();

    int w = tid >> 5, l = tid & 31;
    int vb = blockIdx.x * 256 + w * 32;
    float2 bp = ((const float2*)b1)[l];
    float4 wA0 = sW[2 * l],      wA1 = sW[2 * l + 1];
    float4 wX0 = sW[64 + 2 * l], wX1 = sW[64 + 2 * l + 1];
    __half2* H = (__half2*)g_h;
    float s0 = 0.f, s1 = 0.f, q0 = 0.f, q1 = 0.f;
    int curg = -1;
    for (int vi = 0; vi < 32; vi++) {
        int vv = vb + vi;
        if (vv >= NN) break;
        int g = batch[vv];
        if (g != curg) {
            if (curg >= 0) {
                atomicAdd(&g_stats[curg * 128 + 2 * l],         s0);
                atomicAdd(&g_stats[curg * 128 + 2 * l + 1],     s1);
                atomicAdd(&g_stats[curg * 128 + 64 + 2 * l],     q0);
                atomicAdd(&g_stats[curg * 128 + 64 + 2 * l + 1], q1);
                s0 = s1 = q0 = q1 = 0.f;
            }
            curg = g;
        }
        float4 A = sA[w * 32 + vi];
        float4 X = sX[w * 32 + vi];
        float h0 = bp.x + wA0.x * A.x + wA0.y * A.y + wA0.z * A.z + wA0.w * A.w
                        + wX0.x * X.x + wX0.y * X.y + wX0.z * X.z + wX0.w * X.w;
        float h1 = bp.y + wA1.x * A.x + wA1.y * A.y + wA1.z * A.z + wA1.w * A.w
                        + wX1.x * X.x + wX1.y * X.y + wX1.z * X.z + wX1.w * X.w;
        H[vv * 32 + l] = __floats2half2_rn(h0, h1);
        s0 += h0; s1 += h1; q0 += h0 * h0; q1 += h1 * h1;
    }
    if (curg >= 0) {
        atomicAdd(&g_stats[curg * 128 + 2 * l],         s0);
        atomicAdd(&g_stats[curg * 128 + 2 * l + 1],     s1);
        atomicAdd(&g_stats[curg * 128 + 64 + 2 * l],     q0);
        atomicAdd(&g_stats[curg * 128 + 64 + 2 * l + 1], q1);
    }
}

// ---------------- gather (fp16) + bias + stats: h = mean_e yl[src] + yr[v] + b --------
__global__ void __launch_bounds__(256) k_aggstats(const int* __restrict__ batch,
                                                  const float* __restrict__ bias, int so) {
    int w = threadIdx.x >> 5, l = threadIdx.x & 31;
    int vbase = blockIdx.x * 128 + w * 16;
    float2 bp = ((const float2*)bias)[l];
    const __half2* Y  = (const __half2*)g_ylh;
    const __half2* YR = (const __half2*)g_yr;
    __half2* H = (__half2*)g_h;
    float* st = &g_stats[so];
    float s0 = 0.f, s1 = 0.f, q0 = 0.f, q1 = 0.f;
    int curg = -1;
    for (int vi = 0; vi < 16; vi++) {
        int v = vbase + vi;
        if (v >= NN) break;
        int g = batch[v];
        if (g != curg) {
            if (curg >= 0) {
                atomicAdd(&st[curg * 128 + 2 * l],         s0);
                atomicAdd(&st[curg * 128 + 2 * l + 1],     s1);
                atomicAdd(&st[curg * 128 + 64 + 2 * l],     q0);
                atomicAdd(&st[curg * 128 + 64 + 2 * l + 1], q1);
                s0 = s1 = q0 = q1 = 0.f;
            }
            curg = g;
        }
        int r0 = g_rowptr[v], r1 = g_rowptr[v + 1];
        float ax = 0.f, ay = 0.f;
        int e = r0;
        for (; e + 4 <= r1; e += 4) {
            int a = g_col[e], b = g_col[e + 1], c = g_col[e + 2], d = g_col[e + 3];
            float2 p0 = __half22float2(Y[a * 32 + l]);
            float2 p1 = __half22float2(Y[b * 32 + l]);
            float2 p2 = __half22float2(Y[c * 32 + l]);
            float2 p3 = __half22float2(Y[d * 32 + l]);
            ax += p0.x + p1.x + p2.x + p3.x;
            ay += p0.y + p1.y + p2.y + p3.y;
        }
        for (; e < r1; e++) {
            float2 p = __half22float2(Y[g_col[e] * 32 + l]);
            ax += p.x; ay += p.y;
        }
        float invd = 1.0f / (float)max(r1 - r0, 1);
        float2 yr = __half22float2(YR[v * 32 + l]);
        float hx = ax * invd + yr.x + bp.x;
        float hy = ay * invd + yr.y + bp.y;
        H[v * 32 + l] = __floats2half2_rn(hx, hy);
        s0 += hx; s1 += hy; q0 += hx * hx; q1 += hy * hy;
    }
    if (curg >= 0) {
        atomicAdd(&st[curg * 128 + 2 * l],         s0);
        atomicAdd(&st[curg * 128 + 2 * l + 1],     s1);
        atomicAdd(&st[curg * 128 + 64 + 2 * l],     q0);
        atomicAdd(&st[curg * 128 + 64 + 2 * l + 1], q1);
    }
}

#define MMA16816(ac, A0, A1, A2, A3, B0, B1)                                  \
    asm volatile("mma.sync.aligned.m16n8k16.row.col.f32.f16.f16.f32 "         \
                 "{%0,%1,%2,%3}, {%4,%5,%6,%7}, {%8,%9}, {%0,%1,%2,%3};"      \
                 : "+f"(ac[0]), "+f"(ac[1]), "+f"(ac[2]), "+f"(ac[3])         \
                 : "r"(A0), "r"(A1), "r"(A2), "r"(A3), "r"(B0), "r"(B1))

// ---------------- fused GraphNorm(+res)+ReLU + tensor-core GEMM ----------------------
__global__ void __launch_bounds__(128) k_ngemm(int l3, int use_res,
        const float* __restrict__ gamma, const float* __restrict__ beta,
        const float* __restrict__ alpha, const int* __restrict__ batch, int so) {
    __shared__ unsigned int Ah[64 * 32];     // A fp16 [row][word], XOR-swizzled
    __shared__ unsigned int Whi[4096];       // [n][word] swizzled (verbatim copy)
    __shared__ unsigned int Wlo[4096];
    __shared__ float s_am[2][64], s_sc[2][64], s_be[64];
    const unsigned int* GWhi = l3 ? g_W3hi : g_W2hi;
    const unsigned int* GWlo = l3 ? g_W3lo : g_W2lo;
    int tid = threadIdx.x;
    int n0 = blockIdx.x * 64;

    #pragma unroll
    for (int i = tid; i < 1024; i += 128) {
        ((uint4*)Whi)[i] = ((const uint4*)GWhi)[i];
        ((uint4*)Wlo)[i] = ((const uint4*)GWlo)[i];
    }

    int g0 = batch[n0];
    int split = g_gstart[g0 + 1] - n0;
    int g1 = (g0 + 1 < NG) ? g0 + 1 : g0;
    {
        int side = tid >> 6, f = tid & 63;
        int g = side ? g1 : g0;
        float cnt = (float)(g_gstart[g + 1] - g_gstart[g]);
        float ic = 1.0f / cnt;
        float m   = g_stats[so + g * 128 + f] * ic;
        float ex2 = g_stats[so + g * 128 + 64 + f] * ic;
        float al = alpha[f];
        float var = ex2 - (2.0f * al - al * al) * m * m;
        s_sc[side][f] = gamma[f] * rsqrtf(var + EPSV);
        s_am[side][f] = al * m;
        if (side == 0) s_be[f] = beta[f];
    }
    __syncthreads();
    // norm (+res) + relu -> fp16 A tile (swizzled) + fp16 g_xc
    #pragma unroll
    for (int it = 0; it < 8; it++) {
        int idx = it * 512 + tid * 4;
        int row = idx >> 6, k0 = idx & 63;
        int v = n0 + row;
        float4 hv = make_float4(0.f, 0.f, 0.f, 0.f);
        float4 rv = make_float4(0.f, 0.f, 0.f, 0.f);
        if (v < NN) {
            uint2 hraw = *(const uint2*)&g_h[v * 64 + k0];
            float2 hf0 = __half22float2(((__half2*)&hraw)[0]);
            float2 hf1 = __half22float2(((__half2*)&hraw)[1]);
            hv = make_float4(hf0.x, hf0.y, hf1.x, hf1.y);
            if (use_res) {
                uint2 rraw = *(const uint2*)&g_xc[v * 64 + k0];
                float2 rf0 = __half22float2(((__half2*)&rraw)[0]);
                float2 rf1 = __half22float2(((__half2*)&rraw)[1]);
                rv = make_float4(rf0.x, rf0.y, rf1.x, rf1.y);
            }
        }
        int side = row >= split;
        float o[4];
        #pragma unroll
        for (int j = 0; j < 4; j++) {
            float h = (&hv.x)[j];
            float val = (h - s_am[side][k0 + j]) * s_sc[side][k0 + j] + s_be[k0 + j] + (&rv.x)[j];
            val = fmaxf(val, 0.f);
            o[j] = val;
        }
        int w0 = k0 >> 1;                 // even
        int mask = (row & 7) << 2;
        __half2 p0 = __floats2half2_rn(o[0], o[1]);
        __half2 p1 = __floats2half2_rn(o[2], o[3]);
        Ah[row * 32 + (w0 ^ mask)]       = *(unsigned int*)&p0;
        Ah[row * 32 + ((w0 + 1) ^ mask)] = *(unsigned int*)&p1;
        if (v < NN) {
            uint2 oo;
            ((__half2*)&oo)[0] = p0;
            ((__half2*)&oo)[1] = p1;
            *(uint2*)&g_xc[v * 64 + k0] = oo;
        }
    }
    __syncthreads();

    int lane = tid & 31, wid = tid >> 5;
    int grp = lane >> 2, qid = lane & 3;
    int mbase = wid * 16;
    int rowA = mbase + grp;
    int maskA = grp << 2;
    float acc[16][4];
    #pragma unroll
    for (int j = 0; j < 16; j++)
        #pragma unroll
        for (int c = 0; c < 4; c++) acc[j][c] = 0.f;

    #pragma unroll
    for (int ks = 0; ks < 4; ks++) {
        int wa = ks * 8 + qid;
        unsigned int a0 = Ah[rowA * 32 + (wa ^ maskA)];
        unsigned int a1 = Ah[(rowA + 8) * 32 + (wa ^ maskA)];
        unsigned int a2 = Ah[rowA * 32 + ((wa + 4) ^ maskA)];
        unsigned int a3 = Ah[(rowA + 8) * 32 + ((wa + 4) ^ maskA)];
        #pragma unroll
        for (int j = 0; j < 16; j++) {
            int n = j * 8 + grp;
            unsigned int b0 = Whi[n * 32 + (wa ^ maskA)];
            unsigned int b1 = Whi[n * 32 + ((wa + 4) ^ maskA)];
            MMA16816(acc[j], a0, a1, a2, a3, b0, b1);
            unsigned int c0 = Wlo[n * 32 + (wa ^ maskA)];
            unsigned int c1 = Wlo[n * 32 + ((wa + 4) ^ maskA)];
            MMA16816(acc[j], a0, a1, a2, a3, c0, c1);
        }
    }

    // epilogue: n-tiles 0..7 -> g_ylh (fp16), 8..15 -> g_yr (fp16)
    int v0 = n0 + mbase + grp;
    int v1 = v0 + 8;
    #pragma unroll
    for (int j = 0; j < 16; j++) {
        int n = j * 8 + qid * 2;
        __half2 d01 = __floats2half2_rn(acc[j][0], acc[j][1]);
        __half2 d23 = __floats2half2_rn(acc[j][2], acc[j][3]);
        if (j < 8) {
            if (v0 < NN) *(__half2*)&g_ylh[v0 * 64 + n] = d01;
            if (v1 < NN) *(__half2*)&g_ylh[v1 * 64 + n] = d23;
        } else {
            int nn = n - 64;
            if (v0 < NN) *(__half2*)&g_yr[v0 * 64 + nn] = d01;
            if (v1 < NN) *(__half2*)&g_yr[v1 * 64 + nn] = d23;
        }
    }
}

// ---------------- layer-3 norm + residual + relu + mean pool + linear head -----------
__global__ void k_norm3pool(const float* __restrict__ gamma, const float* __restrict__ beta,
                            const float* __restrict__ alpha, int so,
                            const float* __restrict__ Wlin, const float* __restrict__ blin,
                            float* __restrict__ out) {
    int g = blockIdx.x;
    int t = threadIdx.x; // 256
    int f2 = t & 31, sub = t >> 5;  // 32 half2-cols x 8 subgroups
    int s = g_gstart[g], e = g_gstart[g + 1];
    float cnt = (float)(e - s);
    float ic = 1.0f / cnt;
    float S0 = g_stats[so + g * 128 + 2 * f2],     S1 = g_stats[so + g * 128 + 2 * f2 + 1];
    float Q0 = g_stats[so + g * 128 + 64 + 2 * f2], Q1 = g_stats[so + g * 128 + 64 + 2 * f2 + 1];
    float al0 = alpha[2 * f2], al1 = alpha[2 * f2 + 1];
    float m0 = S0 * ic, m1 = S1 * ic;
    float var0 = Q0 * ic - (2.0f * al0 - al0 * al0) * m0 * m0;
    float var1 = Q1 * ic - (2.0f * al1 - al1 * al1) * m1 * m1;
    float inv0 = rsqrtf(var0 + EPSV), inv1 = rsqrtf(var1 + EPSV);
    float ga0 = gamma[2 * f2], ga1 = gamma[2 * f2 + 1];
    float be0 = beta[2 * f2],  be1 = beta[2 * f2 + 1];
    float am0 = al0 * m0, am1 = al1 * m1;
    const __half2* H = (const __half2*)g_h;
    const __half2* XC = (const __half2*)g_xc;
    float p0 = 0.f, p1 = 0.f;
    for (int v = s + sub; v < e; v += 8) {
        float2 hv = __half22float2(H[v * 32 + f2]);
        float2 xv = __half22float2(XC[v * 32 + f2]);
        float y0 = ga0 * (hv.x - am0) * inv0 + be0 + xv.x;
        float y1 = ga1 * (hv.y - am1) * inv1 + be1 + xv.y;
        p0 += fmaxf(y0, 0.f);
        p1 += fmaxf(y1, 0.f);
    }
    __shared__ float sh[2][256];
    __shared__ float pool[64];
    sh[0][t] = p0; sh[1][t] = p1;
    __syncthreads();
    if (sub < 2) {
        int ff = sub;  // 0 or 1
        float acc = 0.f;
        #pragma unroll
        for (int jj = 0; jj < 8; jj++) acc += sh[ff][jj * 32 + f2];
        pool[2 * f2 + ff] = acc * ic;
        g_pooled[g * 64 + 2 * f2 + ff] = acc * ic;
    }
    __syncthreads();
    if (t < 3) {
        float s0 = blin[t];
        #pragma unroll 8
        for (int ff = 0; ff < 64; ff++) s0 += pool[ff] * Wlin[t * 64 + ff];
        out[g * 3 + t] = s0;
    }
}

// ---------------- launch ----------------
extern "C" void kernel_launch(void* const* d_in, const int* in_sizes, int n_in,
                              void* d_out, int out_size) {
    const float* x     = (const float*)d_in[0];
    const int*   ei    = (const int*)d_in[1];
    const int*   batch = (const int*)d_in[2];
    const float* W1l = (const float*)d_in[3];
    const float* b1  = (const float*)d_in[4];
    const float* W1r = (const float*)d_in[5];
    const float* W2l = (const float*)d_in[6];
    const float* b2  = (const float*)d_in[7];
    const float* W2r = (const float*)d_in[8];
    const float* W3l = (const float*)d_in[9];
    const float* b3  = (const float*)d_in[10];
    const float* W3r = (const float*)d_in[11];
    const float* g1  = (const float*)d_in[12];
    const float* be1 = (const float*)d_in[13];
    const float* a1  = (const float*)d_in[14];
    const float* g2  = (const float*)d_in[15];
    const float* be2 = (const float*)d_in[16];
    const float* a2  = (const float*)d_in[17];
    const float* g3  = (const float*)d_in[18];
    const float* be3 = (const float*)d_in[19];
    const float* a3  = (const float*)d_in[20];
    const float* Wlin = (const float*)d_in[21];
    const float* blin = (const float*)d_in[22];
    float* out = (float*)d_out;

    k_prep<<<(NN + 255) / 256, 256>>>(batch, W1l, W1r, W2l, W2r, W3l, W3r);
    k_hist<<<(NE + 255) / 256, 256>>>(ei);
    k_scan1<<<NSC, 1024>>>();
    k_scan3<<<NSC, 1024>>>();
    k_scatter<<<(NE + 255) / 256, 256>>>(ei);

    const int AGG_BLOCKS = (NN + 127) / 128;
    const int GEMM_BLOCKS = (NN + 63) / 64;

    k_layer1<<<(NN + 255) / 256, 256>>>(x, b1, batch);
    k_ngemm<<<GEMM_BLOCKS, 128>>>(0, 0, g1, be1, a1, batch, 0);
    k_aggstats<<<AGG_BLOCKS, 256>>>(batch, b2, NG * 128);
    k_ngemm<<<GEMM_BLOCKS, 128>>>(1, 1, g2, be2, a2, batch, NG * 128);
    k_aggstats<<<AGG_BLOCKS, 256>>>(batch, b3, 2 * NG * 128);

    k_norm3pool<<<NG, 256>>>(g3, be3, a3, 2 * NG * 128, Wlin, blin, out);
}